// round 2
// baseline (speedup 1.0000x reference)
#include <cuda_runtime.h>
#include <cstdint>

typedef unsigned long long u64;

// ---------------- problem constants (fixed shapes) ----------------
constexpr int NB = 4;          // batch
constexpr int NC = 256;        // in channels (cin == f)
constexpr int NO = 256;        // out channels (f)
constexpr int IH = 64, IW = 64;
constexpr int OH = 128, OW = 128;
constexpr int HW = OH * OW;    // 16384
constexpr size_t TENSOR_ELEMS = (size_t)NB * NC * HW;  // 16,777,216

// ---------------- scratch (static device globals; no cudaMalloc) ----------------
__device__ float g_xup [TENSOR_ELEMS];   // upsampled input
__device__ float g_y1  [TENSOR_ELEMS];   // after conv1 + leaky
__device__ float g_skip[TENSOR_ELEMS];   // 1x1 skip
__device__ float g_s1[NB * NC], g_s2[NB * NC];     // style + 1
__device__ float g_d1[NB * NO], g_d2[NB * NO];     // demod factors
__device__ float g_wsq1[NO * NC], g_wsq2[NO * NC]; // sum_kl W^2

// ---------------- packed f32x2 helpers (Blackwell FFMA2) ----------------
__device__ __forceinline__ u64 fma2(u64 a, u64 b, u64 c) {
    u64 d;
    asm("fma.rn.f32x2 %0, %1, %2, %3;" : "=l"(d) : "l"(a), "l"(b), "l"(c));
    return d;
}
__device__ __forceinline__ u64 pack2(float lo, float hi) {
    u64 d;
    asm("mov.b64 %0, {%1, %2};" : "=l"(d) : "f"(lo), "f"(hi));
    return d;
}
__device__ __forceinline__ float2 unpack2(u64 v) {
    float2 r;
    asm("mov.b64 {%0, %1}, %2;" : "=f"(r.x), "=f"(r.y) : "l"(v));
    return r;
}

// ---------------- 1) bilinear 2x upsample (align_corners=False, edge clamp) ----------------
__global__ void k_upsample(const float* __restrict__ x) {
    int idx = blockIdx.x * 256 + threadIdx.x;            // 16,777,216 total
    int ox = idx & (OW - 1);
    int oy = (idx >> 7) & (OH - 1);
    int bc = idx >> 14;                                   // 0..1023 (b*C + c)

    int y0, x0; float fy, fx;
    if (oy & 1) { y0 = oy >> 1;       fy = 0.25f; }
    else        { y0 = (oy >> 1) - 1; fy = 0.75f; }
    if (ox & 1) { x0 = ox >> 1;       fx = 0.25f; }
    else        { x0 = (ox >> 1) - 1; fx = 0.75f; }
    int y1i = min(y0 + 1, IH - 1); y0 = max(y0, 0);
    int x1i = min(x0 + 1, IW - 1); x0 = max(x0, 0);

    const float* p = x + (size_t)bc * (IH * IW);
    float v00 = p[y0  * IW + x0], v01 = p[y0  * IW + x1i];
    float v10 = p[y1i * IW + x0], v11 = p[y1i * IW + x1i];
    float vt = v00 + fx * (v01 - v00);
    float vb = v10 + fx * (v11 - v10);
    g_xup[idx] = vt + fy * (vb - vt);
}

// ---------------- 2) styles: s = istyle @ W^T + b + 1 ----------------
__global__ void k_styles(const float* __restrict__ istyle,
                         const float* __restrict__ w1, const float* __restrict__ b1,
                         const float* __restrict__ w2, const float* __restrict__ b2) {
    int b = blockIdx.x & 3;
    int which = blockIdx.x >> 2;
    int c = threadIdx.x;
    const float* wrow = (which ? w2 : w1) + (size_t)c * 256;
    const float* ist = istyle + b * 256;
    float acc = (which ? b2 : b1)[c];
#pragma unroll 8
    for (int k = 0; k < 256; ++k) acc += ist[k] * wrow[k];
    (which ? g_s2 : g_s1)[b * 256 + c] = acc + 1.0f;
}

// ---------------- 3) wsq[o,c] = sum_kl W[o,c,k,l]^2 ----------------
__global__ void k_wsq(const float* __restrict__ w1, const float* __restrict__ w2) {
    int which = blockIdx.y;
    int i = blockIdx.x * 256 + threadIdx.x;               // 0..65535
    const float* w = (which ? w2 : w1) + (size_t)i * 9;
    float s = 0.0f;
#pragma unroll
    for (int k = 0; k < 9; ++k) { float v = w[k]; s += v * v; }
    (which ? g_wsq2 : g_wsq1)[i] = s;
}

// ---------------- 4) demod[b,o] = rsqrt(sum_c wsq[o,c]*s[b,c]^2 + eps) ----------------
__global__ void k_demod() {
    int o = blockIdx.x, b = blockIdx.y, which = blockIdx.z;
    int c = threadIdx.x;
    const float* wsq = which ? g_wsq2 : g_wsq1;
    const float* s   = which ? g_s2  : g_s1;
    float sv = s[b * NC + c];
    float v = wsq[o * NC + c] * sv * sv;
    __shared__ float red[256];
    red[c] = v;
    __syncthreads();
    for (int st = 128; st; st >>= 1) {
        if (c < st) red[c] += red[c + st];
        __syncthreads();
    }
    if (c == 0) (which ? g_d2 : g_d1)[b * NO + o] = rsqrtf(red[0] + 1e-8f);
}

// ---------------- 5) 1x1 skip GEMM: g_skip[b,o,p] = sum_c w[o,c] * g_xup[b,c,p] ----------------
__global__ __launch_bounds__(256) void k_skip(const float* __restrict__ wgt) {
    __shared__ __align__(16) float si[16][256];
    __shared__ __align__(16) float swt[16][32];
    int t = threadIdx.x;
    int pix0 = blockIdx.x * 256;
    int ocBase = blockIdx.y * 32;
    int b = blockIdx.z;
    int pixgrp = t & 63, ocg = t >> 6;
    int p4 = pixgrp * 4;

    u64 acc[4][4] = {};
    const float* inB = g_xup + (size_t)b * NC * HW + pix0;

    for (int cb = 0; cb < NC; cb += 16) {
        for (int e = t; e < 16 * 256; e += 256) {
            int c = e >> 8, p = e & 255;
            si[c][p] = inB[(size_t)(cb + c) * HW + p];
        }
        // FIX (R1): 512 elements must be loaded by 256 threads -> strided loop.
        for (int e = t; e < 16 * 32; e += 256) {
            int c = e >> 5, oc = e & 31;
            swt[c][oc] = wgt[(size_t)(ocBase + oc) * NC + cb + c];
        }
        __syncthreads();
#pragma unroll 1
        for (int c = 0; c < 16; ++c) {
            float4 a = *(const float4*)&si[c][p4];
            u64 dv0 = pack2(a.x, a.x), dv1 = pack2(a.y, a.y);
            u64 dv2 = pack2(a.z, a.z), dv3 = pack2(a.w, a.w);
            const u64* wp = (const u64*)&swt[c][ocg * 8];
#pragma unroll
            for (int op = 0; op < 4; ++op) {
                u64 w2p = wp[op];
                acc[op][0] = fma2(dv0, w2p, acc[op][0]);
                acc[op][1] = fma2(dv1, w2p, acc[op][1]);
                acc[op][2] = fma2(dv2, w2p, acc[op][2]);
                acc[op][3] = fma2(dv3, w2p, acc[op][3]);
            }
        }
        __syncthreads();
    }
#pragma unroll
    for (int op = 0; op < 4; ++op) {
        int o0 = ocBase + ocg * 8 + op * 2;
        float* o_lo = g_skip + (size_t)(b * NO + o0) * HW + pix0 + p4;
        float* o_hi = o_lo + HW;
#pragma unroll
        for (int j = 0; j < 4; ++j) {
            float2 v = unpack2(acc[op][j]);
            o_lo[j] = v.x;
            o_hi[j] = v.y;
        }
    }
}

// ---------------- 6/7) modulated 3x3 conv ----------------
// MODE 0: in=g_xup, scale=s1, demod=d1, out=g_y1, no skip.
// MODE 1: in=g_y1,  scale=s2, demod=d2, out=param, + g_skip.
// y = leaky( demod[b,o] * conv(x * s[b,c], W) + bnoise[o] (+ skip) )
template <int MODE>
__global__ __launch_bounds__(256) void k_conv(const float* __restrict__ wgt,
                                              const float* __restrict__ bnoise,
                                              float* __restrict__ outp) {
    constexpr int CC = 8;
    __shared__ __align__(16) float sin_[CC][10][36];    // input tile + halo (34 cols used)
    __shared__ __align__(16) float sw[CC][9][32];       // weights [c][tap][oc]

    const float* in = (MODE == 0) ? g_xup : g_y1;
    const float* s  = (MODE == 0) ? g_s1  : g_s2;
    const float* dm = (MODE == 0) ? g_d1  : g_d2;
    float* out      = (MODE == 0) ? g_y1  : outp;

    int t = threadIdx.x;
    int tx0 = (blockIdx.x & 3) * 32;    // 4 col tiles
    int ty0 = (blockIdx.x >> 2) * 8;    // 16 row tiles
    int ocBase = blockIdx.y * 32;
    int b = blockIdx.z;

    int pixgrp = t & 63, ocg = t >> 6;
    int row  = pixgrp >> 3;             // 0..7
    int colb = (pixgrp & 7) * 4;        // 0..28

    u64 acc[4][4] = {};                 // [oc-pair][pixel]
    const float* inB = in + (size_t)b * NC * HW;
    const float* sB  = s + b * NC;

    for (int cb = 0; cb < NC; cb += CC) {
        // load input tile (pre-scaled by s[b,c]); zero-pad outside image
        for (int e = t; e < CC * 340; e += 256) {
            int c = e / 340; int rem = e - c * 340;
            int r = rem / 34; int xx = rem - r * 34;
            int gy = ty0 - 1 + r, gx = tx0 - 1 + xx;
            float v = 0.0f;
            if ((unsigned)gy < OH && (unsigned)gx < OW)
                v = inB[(size_t)(cb + c) * HW + gy * OW + gx] * sB[cb + c];
            sin_[c][r][xx] = v;
        }
        // load weights, layout [c][tap][oc] so oc pairs are LDS.64
        for (int e = t; e < CC * 288; e += 256) {
            int c = e / 288; int rem = e - c * 288;
            int kl = rem >> 5; int oc = rem & 31;
            sw[c][kl][oc] = wgt[((size_t)(ocBase + oc) * NC + cb + c) * 9 + kl];
        }
        __syncthreads();

#pragma unroll 1
        for (int c = 0; c < CC; ++c) {
            // 3x6 input window, each value duplicated into both f32x2 lanes
            u64 wv[3][6];
#pragma unroll
            for (int dy = 0; dy < 3; ++dy) {
                const float* p = &sin_[c][row + dy][colb];
                float4 a = *(const float4*)p;
                float2 bb = *(const float2*)(p + 4);
                wv[dy][0] = pack2(a.x, a.x);  wv[dy][1] = pack2(a.y, a.y);
                wv[dy][2] = pack2(a.z, a.z);  wv[dy][3] = pack2(a.w, a.w);
                wv[dy][4] = pack2(bb.x, bb.x); wv[dy][5] = pack2(bb.y, bb.y);
            }
#pragma unroll
            for (int dy = 0; dy < 3; ++dy)
#pragma unroll
                for (int dx = 0; dx < 3; ++dx) {
                    const u64* wp = (const u64*)&sw[c][dy * 3 + dx][ocg * 8];
#pragma unroll
                    for (int op = 0; op < 4; ++op) {
                        u64 w2p = wp[op];     // (w[oc], w[oc+1]) packed
                        acc[op][0] = fma2(wv[dy][dx + 0], w2p, acc[op][0]);
                        acc[op][1] = fma2(wv[dy][dx + 1], w2p, acc[op][1]);
                        acc[op][2] = fma2(wv[dy][dx + 2], w2p, acc[op][2]);
                        acc[op][3] = fma2(wv[dy][dx + 3], w2p, acc[op][3]);
                    }
                }
        }
        __syncthreads();
    }

    // epilogue: demod, +noise bias, (+skip), leaky relu
    int oy = ty0 + row, ox = tx0 + colb;
#pragma unroll
    for (int op = 0; op < 4; ++op) {
        int o0 = ocBase + ocg * 8 + op * 2;
        float d0  = dm[b * NO + o0];
        float d1v = dm[b * NO + o0 + 1];
        float n0 = bnoise[o0], n1 = bnoise[o0 + 1];
        size_t base = ((size_t)(b * NO + o0) * OH + oy) * OW + ox;
#pragma unroll
        for (int j = 0; j < 4; ++j) {
            float2 v = unpack2(acc[op][j]);
            float r0 = v.x * d0  + n0;
            float r1 = v.y * d1v + n1;
            if (MODE == 1) {
                r0 += g_skip[base + j];
                r1 += g_skip[base + HW + j];
            }
            out[base + j]      = (r0 >= 0.0f) ? r0 : 0.2f * r0;
            out[base + HW + j] = (r1 >= 0.0f) ? r1 : 0.2f * r1;
        }
    }
}

// ---------------- launch ----------------
extern "C" void kernel_launch(void* const* d_in, const int* in_sizes, int n_in,
                              void* d_out, int out_size) {
    (void)in_sizes; (void)n_in; (void)out_size;
    const float* x         = (const float*)d_in[0];
    const float* istyle    = (const float*)d_in[1];
    const float* w_style1  = (const float*)d_in[2];
    const float* b_style1  = (const float*)d_in[3];
    const float* w_style2  = (const float*)d_in[4];
    const float* b_style2  = (const float*)d_in[5];
    // d_in[6] = w_noise1 (unused: inoise == 0), d_in[8] = w_noise2 (unused)
    const float* b_noise1  = (const float*)d_in[7];
    const float* b_noise2  = (const float*)d_in[9];
    const float* conv1_w   = (const float*)d_in[10];
    const float* conv2_w   = (const float*)d_in[11];
    const float* conv1x1_w = (const float*)d_in[12];
    float* out = (float*)d_out;

    k_upsample<<<65536, 256>>>(x);
    k_styles<<<8, 256>>>(istyle, w_style1, b_style1, w_style2, b_style2);
    k_wsq<<<dim3(256, 2), 256>>>(conv1_w, conv2_w);
    k_demod<<<dim3(256, 4, 2), 256>>>();
    k_skip<<<dim3(64, 8, 4), 256>>>(conv1x1_w);
    k_conv<0><<<dim3(64, 8, 4), 256>>>(conv1_w, b_noise1, nullptr);
    k_conv<1><<<dim3(64, 8, 4), 256>>>(conv2_w, b_noise2, out);
}

// round 3
// speedup vs baseline: 1.0005x; 1.0005x over previous
#include <cuda_runtime.h>
#include <cstdint>

typedef unsigned long long u64;

// ---------------- problem constants (fixed shapes) ----------------
constexpr int NB = 4;          // batch
constexpr int NC = 256;        // in channels (cin == f)
constexpr int NO = 256;        // out channels (f)
constexpr int IH = 64, IW = 64;
constexpr int OH = 128, OW = 128;
constexpr int HW = OH * OW;    // 16384
constexpr size_t TENSOR_ELEMS = (size_t)NB * NC * HW;  // 16,777,216

// ---------------- scratch (static device globals; no cudaMalloc) ----------------
__device__ float g_xup [TENSOR_ELEMS];   // upsampled input
__device__ float g_y1  [TENSOR_ELEMS];   // after conv1 + leaky
__device__ float g_skip[TENSOR_ELEMS];   // 1x1 skip
__device__ float g_s1[NB * NC], g_s2[NB * NC];     // style + 1
__device__ float g_d1[NB * NO], g_d2[NB * NO];     // demod factors
__device__ float g_wsq1[NO * NC], g_wsq2[NO * NC]; // sum_kl W^2

// ---------------- packed f32x2 helpers (Blackwell FFMA2) ----------------
__device__ __forceinline__ u64 fma2(u64 a, u64 b, u64 c) {
    u64 d;
    asm("fma.rn.f32x2 %0, %1, %2, %3;" : "=l"(d) : "l"(a), "l"(b), "l"(c));
    return d;
}
__device__ __forceinline__ u64 pack2(float lo, float hi) {
    u64 d;
    asm("mov.b64 %0, {%1, %2};" : "=l"(d) : "f"(lo), "f"(hi));
    return d;
}
__device__ __forceinline__ float2 unpack2(u64 v) {
    float2 r;
    asm("mov.b64 {%0, %1}, %2;" : "=f"(r.x), "=f"(r.y) : "l"(v));
    return r;
}

// ---------------- 1) bilinear 2x upsample (align_corners=False, edge clamp) ----------------
__global__ void k_upsample(const float* __restrict__ x) {
    int idx = blockIdx.x * 256 + threadIdx.x;            // 16,777,216 total
    int ox = idx & (OW - 1);
    int oy = (idx >> 7) & (OH - 1);
    int bc = idx >> 14;                                   // 0..1023 (b*C + c)

    int y0, x0; float fy, fx;
    if (oy & 1) { y0 = oy >> 1;       fy = 0.25f; }
    else        { y0 = (oy >> 1) - 1; fy = 0.75f; }
    if (ox & 1) { x0 = ox >> 1;       fx = 0.25f; }
    else        { x0 = (ox >> 1) - 1; fx = 0.75f; }
    int y1i = min(y0 + 1, IH - 1); y0 = max(y0, 0);
    int x1i = min(x0 + 1, IW - 1); x0 = max(x0, 0);

    const float* p = x + (size_t)bc * (IH * IW);
    float v00 = p[y0  * IW + x0], v01 = p[y0  * IW + x1i];
    float v10 = p[y1i * IW + x0], v11 = p[y1i * IW + x1i];
    float vt = v00 + fx * (v01 - v00);
    float vb = v10 + fx * (v11 - v10);
    g_xup[idx] = vt + fy * (vb - vt);
}

// ---------------- 2) styles: s = istyle @ W^T + b + 1 ----------------
__global__ void k_styles(const float* __restrict__ istyle,
                         const float* __restrict__ w1, const float* __restrict__ b1,
                         const float* __restrict__ w2, const float* __restrict__ b2) {
    int b = blockIdx.x & 3;
    int which = blockIdx.x >> 2;
    int c = threadIdx.x;
    const float* wrow = (which ? w2 : w1) + (size_t)c * 256;
    const float* ist = istyle + b * 256;
    float acc = (which ? b2 : b1)[c];
#pragma unroll 8
    for (int k = 0; k < 256; ++k) acc += ist[k] * wrow[k];
    (which ? g_s2 : g_s1)[b * 256 + c] = acc + 1.0f;
}

// ---------------- 3) wsq[o,c] = sum_kl W[o,c,k,l]^2 ----------------
__global__ void k_wsq(const float* __restrict__ w1, const float* __restrict__ w2) {
    int which = blockIdx.y;
    int i = blockIdx.x * 256 + threadIdx.x;               // 0..65535
    const float* w = (which ? w2 : w1) + (size_t)i * 9;
    float s = 0.0f;
#pragma unroll
    for (int k = 0; k < 9; ++k) { float v = w[k]; s += v * v; }
    (which ? g_wsq2 : g_wsq1)[i] = s;
}

// ---------------- 4) demod[b,o] = rsqrt(sum_c wsq[o,c]*s[b,c]^2 + eps) ----------------
__global__ void k_demod() {
    int o = blockIdx.x, b = blockIdx.y, which = blockIdx.z;
    int c = threadIdx.x;
    const float* wsq = which ? g_wsq2 : g_wsq1;
    const float* s   = which ? g_s2  : g_s1;
    float sv = s[b * NC + c];
    float v = wsq[o * NC + c] * sv * sv;
    __shared__ float red[256];
    red[c] = v;
    __syncthreads();
    for (int st = 128; st; st >>= 1) {
        if (c < st) red[c] += red[c + st];
        __syncthreads();
    }
    if (c == 0) (which ? g_d2 : g_d1)[b * NO + o] = rsqrtf(red[0] + 1e-8f);
}

// ---------------- 5) 1x1 skip GEMM: g_skip[b,o,p] = sum_c w[o,c] * g_xup[b,c,p] ----------------
__global__ __launch_bounds__(256) void k_skip(const float* __restrict__ wgt) {
    __shared__ __align__(16) float si[16][256];
    __shared__ __align__(16) float swt[16][32];
    int t = threadIdx.x;
    int pix0 = blockIdx.x * 256;
    int ocBase = blockIdx.y * 32;
    int b = blockIdx.z;
    int pixgrp = t & 63, ocg = t >> 6;
    int p4 = pixgrp * 4;

    u64 acc[4][4] = {};
    const float* inB = g_xup + (size_t)b * NC * HW + pix0;

    for (int cb = 0; cb < NC; cb += 16) {
        for (int e = t; e < 16 * 256; e += 256) {
            int c = e >> 8, p = e & 255;
            si[c][p] = inB[(size_t)(cb + c) * HW + p];
        }
        // FIX (R1): 512 elements must be loaded by 256 threads -> strided loop.
        for (int e = t; e < 16 * 32; e += 256) {
            int c = e >> 5, oc = e & 31;
            swt[c][oc] = wgt[(size_t)(ocBase + oc) * NC + cb + c];
        }
        __syncthreads();
#pragma unroll 1
        for (int c = 0; c < 16; ++c) {
            float4 a = *(const float4*)&si[c][p4];
            u64 dv0 = pack2(a.x, a.x), dv1 = pack2(a.y, a.y);
            u64 dv2 = pack2(a.z, a.z), dv3 = pack2(a.w, a.w);
            const u64* wp = (const u64*)&swt[c][ocg * 8];
#pragma unroll
            for (int op = 0; op < 4; ++op) {
                u64 w2p = wp[op];
                acc[op][0] = fma2(dv0, w2p, acc[op][0]);
                acc[op][1] = fma2(dv1, w2p, acc[op][1]);
                acc[op][2] = fma2(dv2, w2p, acc[op][2]);
                acc[op][3] = fma2(dv3, w2p, acc[op][3]);
            }
        }
        __syncthreads();
    }
#pragma unroll
    for (int op = 0; op < 4; ++op) {
        int o0 = ocBase + ocg * 8 + op * 2;
        float* o_lo = g_skip + (size_t)(b * NO + o0) * HW + pix0 + p4;
        float* o_hi = o_lo + HW;
#pragma unroll
        for (int j = 0; j < 4; ++j) {
            float2 v = unpack2(acc[op][j]);
            o_lo[j] = v.x;
            o_hi[j] = v.y;
        }
    }
}

// ---------------- 6/7) modulated 3x3 conv ----------------
// MODE 0: in=g_xup, scale=s1, demod=d1, out=g_y1, no skip.
// MODE 1: in=g_y1,  scale=s2, demod=d2, out=param, + g_skip.
// y = leaky( demod[b,o] * conv(x * s[b,c], W) + bnoise[o] (+ skip) )
template <int MODE>
__global__ __launch_bounds__(256) void k_conv(const float* __restrict__ wgt,
                                              const float* __restrict__ bnoise,
                                              float* __restrict__ outp) {
    constexpr int CC = 8;
    __shared__ __align__(16) float sin_[CC][10][36];    // input tile + halo (34 cols used)
    __shared__ __align__(16) float sw[CC][9][32];       // weights [c][tap][oc]

    const float* in = (MODE == 0) ? g_xup : g_y1;
    const float* s  = (MODE == 0) ? g_s1  : g_s2;
    const float* dm = (MODE == 0) ? g_d1  : g_d2;
    float* out      = (MODE == 0) ? g_y1  : outp;

    int t = threadIdx.x;
    int tx0 = (blockIdx.x & 3) * 32;    // 4 col tiles
    int ty0 = (blockIdx.x >> 2) * 8;    // 16 row tiles
    int ocBase = blockIdx.y * 32;
    int b = blockIdx.z;

    int pixgrp = t & 63, ocg = t >> 6;
    int row  = pixgrp >> 3;             // 0..7
    int colb = (pixgrp & 7) * 4;        // 0..28

    u64 acc[4][4] = {};                 // [oc-pair][pixel]
    const float* inB = in + (size_t)b * NC * HW;
    const float* sB  = s + b * NC;

    for (int cb = 0; cb < NC; cb += CC) {
        // load input tile (pre-scaled by s[b,c]); zero-pad outside image
        for (int e = t; e < CC * 340; e += 256) {
            int c = e / 340; int rem = e - c * 340;
            int r = rem / 34; int xx = rem - r * 34;
            int gy = ty0 - 1 + r, gx = tx0 - 1 + xx;
            float v = 0.0f;
            if ((unsigned)gy < OH && (unsigned)gx < OW)
                v = inB[(size_t)(cb + c) * HW + gy * OW + gx] * sB[cb + c];
            sin_[c][r][xx] = v;
        }
        // load weights, layout [c][tap][oc] so oc pairs are LDS.64
        for (int e = t; e < CC * 288; e += 256) {
            int c = e / 288; int rem = e - c * 288;
            int kl = rem >> 5; int oc = rem & 31;
            sw[c][kl][oc] = wgt[((size_t)(ocBase + oc) * NC + cb + c) * 9 + kl];
        }
        __syncthreads();

#pragma unroll 1
        for (int c = 0; c < CC; ++c) {
            // 3x6 input window, each value duplicated into both f32x2 lanes
            u64 wv[3][6];
#pragma unroll
            for (int dy = 0; dy < 3; ++dy) {
                const float* p = &sin_[c][row + dy][colb];
                float4 a = *(const float4*)p;
                float2 bb = *(const float2*)(p + 4);
                wv[dy][0] = pack2(a.x, a.x);  wv[dy][1] = pack2(a.y, a.y);
                wv[dy][2] = pack2(a.z, a.z);  wv[dy][3] = pack2(a.w, a.w);
                wv[dy][4] = pack2(bb.x, bb.x); wv[dy][5] = pack2(bb.y, bb.y);
            }
#pragma unroll
            for (int dy = 0; dy < 3; ++dy)
#pragma unroll
                for (int dx = 0; dx < 3; ++dx) {
                    const u64* wp = (const u64*)&sw[c][dy * 3 + dx][ocg * 8];
#pragma unroll
                    for (int op = 0; op < 4; ++op) {
                        u64 w2p = wp[op];     // (w[oc], w[oc+1]) packed
                        acc[op][0] = fma2(wv[dy][dx + 0], w2p, acc[op][0]);
                        acc[op][1] = fma2(wv[dy][dx + 1], w2p, acc[op][1]);
                        acc[op][2] = fma2(wv[dy][dx + 2], w2p, acc[op][2]);
                        acc[op][3] = fma2(wv[dy][dx + 3], w2p, acc[op][3]);
                    }
                }
        }
        __syncthreads();
    }

    // epilogue: demod, +noise bias, (+skip), leaky relu
    int oy = ty0 + row, ox = tx0 + colb;
#pragma unroll
    for (int op = 0; op < 4; ++op) {
        int o0 = ocBase + ocg * 8 + op * 2;
        float d0  = dm[b * NO + o0];
        float d1v = dm[b * NO + o0 + 1];
        float n0 = bnoise[o0], n1 = bnoise[o0 + 1];
        size_t base = ((size_t)(b * NO + o0) * OH + oy) * OW + ox;
#pragma unroll
        for (int j = 0; j < 4; ++j) {
            float2 v = unpack2(acc[op][j]);
            float r0 = v.x * d0  + n0;
            float r1 = v.y * d1v + n1;
            if (MODE == 1) {
                r0 += g_skip[base + j];
                r1 += g_skip[base + HW + j];
            }
            out[base + j]      = (r0 >= 0.0f) ? r0 : 0.2f * r0;
            out[base + HW + j] = (r1 >= 0.0f) ? r1 : 0.2f * r1;
        }
    }
}

// ---------------- launch ----------------
extern "C" void kernel_launch(void* const* d_in, const int* in_sizes, int n_in,
                              void* d_out, int out_size) {
    (void)in_sizes; (void)n_in; (void)out_size;
    const float* x         = (const float*)d_in[0];
    const float* istyle    = (const float*)d_in[1];
    const float* w_style1  = (const float*)d_in[2];
    const float* b_style1  = (const float*)d_in[3];
    const float* w_style2  = (const float*)d_in[4];
    const float* b_style2  = (const float*)d_in[5];
    // d_in[6] = w_noise1 (unused: inoise == 0), d_in[8] = w_noise2 (unused)
    const float* b_noise1  = (const float*)d_in[7];
    const float* b_noise2  = (const float*)d_in[9];
    const float* conv1_w   = (const float*)d_in[10];
    const float* conv2_w   = (const float*)d_in[11];
    const float* conv1x1_w = (const float*)d_in[12];
    float* out = (float*)d_out;

    k_upsample<<<65536, 256>>>(x);
    k_styles<<<8, 256>>>(istyle, w_style1, b_style1, w_style2, b_style2);
    k_wsq<<<dim3(256, 2), 256>>>(conv1_w, conv2_w);
    k_demod<<<dim3(256, 4, 2), 256>>>();
    k_skip<<<dim3(64, 8, 4), 256>>>(conv1x1_w);
    k_conv<0><<<dim3(64, 8, 4), 256>>>(conv1_w, b_noise1, nullptr);
    k_conv<1><<<dim3(64, 8, 4), 256>>>(conv2_w, b_noise2, out);
}

// round 6
// speedup vs baseline: 2.3799x; 2.3788x over previous
#include <cuda_runtime.h>
#include <cuda_bf16.h>
#include <cstdint>

typedef unsigned long long u64;
typedef unsigned int u32;

// ---------------- problem constants ----------------
constexpr int NB = 4, NC = 256, NO = 256;
constexpr int IH = 64, IW = 64, OH = 128, OW = 128;
constexpr size_t NELEM = (size_t)NB * NC * OH * OW;   // 16,777,216

constexpr u32 SMEM_BYTES = 2 * 98304;                 // 2 stage buffers (A 32KB + B 64KB)

// ---------------- device scratch ----------------
__device__ float g_xt[(size_t)NB * IH * IW * NC];                    // NHWC fp32 (64x64)
__device__ __align__(128) __nv_bfloat16 g_xh[NELEM], g_xl[NELEM];    // NHWC split of upsampled x
__device__ __align__(128) __nv_bfloat16 g_y1h[NELEM], g_y1l[NELEM];  // NHWC split of y1
__device__ __align__(128) __nv_bfloat16 g_B1h[4 * 9 * 256 * 256],  g_B1l[4 * 9 * 256 * 256];
__device__ __align__(128) __nv_bfloat16 g_B2h[4 * 10 * 256 * 256], g_B2l[4 * 10 * 256 * 256];
__device__ float g_s1[NB * NC], g_s2[NB * NC];
__device__ float g_d1[NB * NO], g_d2[NB * NO];
__device__ float g_wsq1[NO * NC], g_wsq2[NO * NC];

// ---------------- helpers ----------------
__device__ __forceinline__ u32 smem_u32(const void* p) {
    u32 a;
    asm("{ .reg .u64 t; cvta.to.shared.u64 t, %1; cvt.u32.u64 %0, t; }" : "=r"(a) : "l"(p));
    return a;
}
__device__ __forceinline__ void ldsm4(u32* r, u32 addr) {
    asm volatile("ldmatrix.sync.aligned.m8n8.x4.shared.b16 {%0,%1,%2,%3}, [%4];"
                 : "=r"(r[0]), "=r"(r[1]), "=r"(r[2]), "=r"(r[3]) : "r"(addr));
}
__device__ __forceinline__ void mma16816(float* d, const u32* a, u32 b0, u32 b1) {
    asm volatile("mma.sync.aligned.m16n8k16.row.col.f32.bf16.bf16.f32 "
                 "{%0,%1,%2,%3}, {%4,%5,%6,%7}, {%8,%9}, {%0,%1,%2,%3};"
                 : "+f"(d[0]), "+f"(d[1]), "+f"(d[2]), "+f"(d[3])
                 : "r"(a[0]), "r"(a[1]), "r"(a[2]), "r"(a[3]), "r"(b0), "r"(b1));
}
__device__ __forceinline__ void cp16(u32 dst, const void* src, u32 sz) {
    asm volatile("cp.async.cg.shared.global [%0], [%1], 16, %2;"
                 :: "r"(dst), "l"(src), "r"(sz) : "memory");
}
__device__ __forceinline__ u32 swz(u32 off) { return off ^ ((off >> 3) & 0x70); }

__device__ __forceinline__ void bsplit(float v, u32& hbits, u32& lbits) {
    __nv_bfloat16 h = __float2bfloat16(v);
    hbits = (u32)__bfloat16_as_ushort(h);
    lbits = (u32)__bfloat16_as_ushort(__float2bfloat16(v - __bfloat162float(h)));
}

// ---------------- 1) NCHW -> NHWC fp32 transpose (64x64) ----------------
__global__ void k_transpose(const float* __restrict__ x) {
    __shared__ float tile[32][33];
    int by = blockIdx.x;                 // b*64 + y
    int b = by >> 6, y = by & 63;
    int cblk = (blockIdx.y >> 1) * 32, xblk = (blockIdx.y & 1) * 32;
    int t = threadIdx.x;
    int ci = t >> 5, xi = t & 31;
#pragma unroll
    for (int p = 0; p < 4; ++p) {
        int c = cblk + p * 8 + ci;
        tile[p * 8 + ci][xi] = x[((size_t)(b * 256 + c) * 64 + y) * 64 + xblk + xi];
    }
    __syncthreads();
    int xi2 = t >> 5, c2 = t & 31;
#pragma unroll
    for (int p = 0; p < 4; ++p) {
        int xx = xblk + p * 8 + xi2;
        g_xt[((size_t)(b * 64 + y) * 64 + xx) * 256 + cblk + c2] = tile[c2][p * 8 + xi2];
    }
}

// ---------------- 2) bilinear 2x upsample + bf16 split (NHWC) ----------------
__global__ void k_upsplit() {
    int i = blockIdx.x * 256 + threadIdx.x;     // 16,777,216
    int c  = i & 255;
    int xo = (i >> 8) & 127;
    int yo = (i >> 15) & 127;
    int b  = i >> 22;

    int y0, x0; float fy, fx;
    if (yo & 1) { y0 = yo >> 1;       fy = 0.25f; }
    else        { y0 = (yo >> 1) - 1; fy = 0.75f; }
    if (xo & 1) { x0 = xo >> 1;       fx = 0.25f; }
    else        { x0 = (xo >> 1) - 1; fx = 0.75f; }
    int y1i = min(y0 + 1, IH - 1); y0 = max(y0, 0);
    int x1i = min(x0 + 1, IW - 1); x0 = max(x0, 0);

    const float* base = g_xt + (size_t)b * IH * IW * 256 + c;
    float v00 = base[(y0  * 64 + x0 ) * 256], v01 = base[(y0  * 64 + x1i) * 256];
    float v10 = base[(y1i * 64 + x0 ) * 256], v11 = base[(y1i * 64 + x1i) * 256];
    float vt = v00 + fx * (v01 - v00);
    float vb = v10 + fx * (v11 - v10);
    float v = vt + fy * (vb - vt);

    __nv_bfloat16 h = __float2bfloat16(v);
    g_xh[i] = h;
    g_xl[i] = __float2bfloat16(v - __bfloat162float(h));
}

// ---------------- 3) styles ----------------
__global__ void k_styles(const float* __restrict__ istyle,
                         const float* __restrict__ w1, const float* __restrict__ b1,
                         const float* __restrict__ w2, const float* __restrict__ b2) {
    int b = blockIdx.x & 3;
    int which = blockIdx.x >> 2;
    int c = threadIdx.x;
    const float* wrow = (which ? w2 : w1) + (size_t)c * 256;
    const float* ist = istyle + b * 256;
    float acc = (which ? b2 : b1)[c];
#pragma unroll 8
    for (int k = 0; k < 256; ++k) acc += ist[k] * wrow[k];
    (which ? g_s2 : g_s1)[b * 256 + c] = acc + 1.0f;
}

// ---------------- 4) wsq ----------------
__global__ void k_wsq(const float* __restrict__ w1, const float* __restrict__ w2) {
    int which = blockIdx.y;
    int i = blockIdx.x * 256 + threadIdx.x;
    const float* w = (which ? w2 : w1) + (size_t)i * 9;
    float s = 0.0f;
#pragma unroll
    for (int k = 0; k < 9; ++k) { float v = w[k]; s += v * v; }
    (which ? g_wsq2 : g_wsq1)[i] = s;
}

// ---------------- 5) demod ----------------
__global__ void k_demod() {
    int o = blockIdx.x, b = blockIdx.y, which = blockIdx.z;
    int c = threadIdx.x;
    const float* wsq = which ? g_wsq2 : g_wsq1;
    const float* s   = which ? g_s2  : g_s1;
    float sv = s[b * NC + c];
    float v = wsq[o * NC + c] * sv * sv;
    __shared__ float red[256];
    red[c] = v;
    __syncthreads();
    for (int st = 128; st; st >>= 1) {
        if (c < st) red[c] += red[c + st];
        __syncthreads();
    }
    if (c == 0) (which ? g_d2 : g_d1)[b * NO + o] = rsqrtf(red[0] + 1e-8f);
}

// ---------------- 6) weight prep: B[b,tap,oc,c] = W[oc,c,tap]*s[b,c], split ----------------
__global__ void k_prepw1(const float* __restrict__ w1) {
    int bt = blockIdx.x;            // b*9+tap
    int b = bt / 9, tap = bt % 9;
    int oc = blockIdx.y, c = threadIdx.x;
    float v = w1[((size_t)oc * 256 + c) * 9 + tap] * g_s1[b * 256 + c];
    __nv_bfloat16 h = __float2bfloat16(v);
    size_t o = ((size_t)bt * 256 + oc) * 256 + c;
    g_B1h[o] = h;
    g_B1l[o] = __float2bfloat16(v - __bfloat162float(h));
}
__global__ void k_prepw2(const float* __restrict__ w2, const float* __restrict__ w1x1) {
    int bt = blockIdx.x;            // b*10+tap
    int b = bt / 10, tap = bt % 10;
    int oc = blockIdx.y, c = threadIdx.x;
    float v;
    if (tap < 9) v = w2[((size_t)oc * 256 + c) * 9 + tap] * g_s2[b * 256 + c];
    else         v = w1x1[(size_t)oc * 256 + c] * (1.0f / g_d2[b * 256 + oc]);
    __nv_bfloat16 h = __float2bfloat16(v);
    size_t o = ((size_t)bt * 256 + oc) * 256 + c;
    g_B2h[o] = h;
    g_B2l[o] = __float2bfloat16(v - __bfloat162float(h));
}

// ---------------- 7) warp-MMA implicit-GEMM modulated conv ----------------
// MODE 0: A = xh/xl (9 taps), epilogue -> y1 split NHWC.
// MODE 1: A = y1h/y1l (taps 0-8) + xh/xl (tap 9 = folded 1x1 skip), epilogue -> out NCHW fp32.
// Per CTA: M=128 pixels (row y0) x N=256 oc. 16 warps (4M x 4N), warp tile m32 x n64.
// Stage buffer layout (98304 B): Ah @0 (16KB), Al @16384, Bh @32768 (32KB), Bl @65536.
template <int MODE>
__global__ void __launch_bounds__(512, 1) k_convhmma(const float* __restrict__ bnoise,
                                                     float* __restrict__ outp) {
    constexpr int NT = (MODE == 0) ? 9 : 10;
    constexpr int S = NT * 4;
    extern __shared__ __align__(1024) char smem[];
    const u32 sb = smem_u32(smem);
    const int t = threadIdx.x;
    const int y0 = blockIdx.x, b = blockIdx.y;
    const float* dmod = (MODE == 0) ? g_d1 : g_d2;

    const int warp = t >> 5, lane = t & 31;
    const int wm = warp & 3, wn = warp >> 2;
    const int li = lane >> 3, lr = lane & 7;

    // ldmatrix addressing (R6 FIX): addr = tile + row*128 + ((colbyte + kadd) ^ ((row&7)*16)).
    // The XOR (swizzle) must be applied to the FULL column-byte offset, not to row alone.
    u32 aRow[2], aXor[2];
#pragma unroll
    for (int mt = 0; mt < 2; ++mt) {
        int row = wm * 32 + mt * 16 + lr + ((li & 1) << 3);
        aRow[mt] = (u32)row << 7;
        aXor[mt] = ((u32)row & 7u) << 4;
    }
    const u32 aCol = ((u32)li >> 1) << 4;
    u32 bRow[4], bXor[4];
#pragma unroll
    for (int p = 0; p < 4; ++p) {
        int row = wn * 64 + p * 16 + lr + ((li >> 1) << 3);
        bRow[p] = (u32)row << 7;
        bXor[p] = ((u32)row & 7u) << 4;
    }
    const u32 bCol = ((u32)li & 1u) << 4;

    float acc[2][8][4];
#pragma unroll
    for (int mt = 0; mt < 2; ++mt)
#pragma unroll
        for (int j = 0; j < 8; ++j)
#pragma unroll
            for (int q = 0; q < 4; ++q) acc[mt][j][q] = 0.0f;

    auto load_stage = [&](int s) {
        int tap = s >> 2, c0 = (s & 3) << 6;
        u32 base = sb + (u32)(s & 1) * 98304u;
        const __nv_bfloat16 *Ah, *Al;
        int dy, dx;
        if (MODE == 1 && tap == 9) { Ah = g_xh; Al = g_xl; dy = 0; dx = 0; }
        else {
            dy = tap / 3 - 1; dx = tap % 3 - 1;
            if (MODE == 0) { Ah = g_xh; Al = g_xl; } else { Ah = g_y1h; Al = g_y1l; }
        }
        int y = y0 + dy;
        bool yok = ((unsigned)y < 128u);
        int yc = min(max(y, 0), 127);
        // A tiles: [128 m][64 c] bf16, h and l
#pragma unroll
        for (int i = 0; i < 4; ++i) {
            int u = t + i * 512;
            int split = u >> 10, rem = u & 1023;
            int m = rem >> 3, j = rem & 7;
            int xx = m + dx;
            bool ok = yok && ((unsigned)xx < 128u);
            int xc = min(max(xx, 0), 127);
            const __nv_bfloat16* src = (split ? Al : Ah)
                + ((size_t)((b * 128 + yc) * 128 + xc) * 256 + c0 + j * 8);
            u32 dst = base + (u32)split * 16384u + swz(((u32)m << 7) + ((u32)j << 4));
            cp16(dst, src, ok ? 16u : 0u);
        }
        // B tiles: [256 oc][64 c] bf16, h and l
        const __nv_bfloat16* Bh = (MODE == 0) ? g_B1h : g_B2h;
        const __nv_bfloat16* Bl = (MODE == 0) ? g_B1l : g_B2l;
        size_t btbase = (size_t)(b * NT + tap) * 65536 + c0;
#pragma unroll
        for (int i = 0; i < 8; ++i) {
            int u = t + i * 512;
            int split = u >> 11, rem = u & 2047;
            int n = rem >> 3, j = rem & 7;
            const __nv_bfloat16* src = (split ? Bl : Bh) + (btbase + n * 256 + j * 8);
            u32 dst = base + 32768u + (u32)split * 32768u + swz(((u32)n << 7) + ((u32)j << 4));
            cp16(dst, src, 16u);
        }
        asm volatile("cp.async.commit_group;" ::: "memory");
    };

    load_stage(0);
    for (int s = 0; s < S; ++s) {
        if (s + 1 < S) {
            load_stage(s + 1);
            asm volatile("cp.async.wait_group 1;" ::: "memory");
        } else {
            asm volatile("cp.async.wait_group 0;" ::: "memory");
        }
        __syncthreads();
        u32 base = sb + (u32)(s & 1) * 98304u;
        // 3 split passes: (Ah,Bh), (Ah,Bl), (Al,Bh)
#pragma unroll
        for (int pass = 0; pass < 3; ++pass) {
            u32 aoff = base + ((pass == 2) ? 16384u : 0u);
            u32 boff = base + 32768u + ((pass == 1) ? 32768u : 0u);
#pragma unroll
            for (int kk = 0; kk < 4; ++kk) {
                u32 kadd = (u32)kk << 5;
                u32 ak = aCol + kadd;
                u32 bk = bCol + kadd;
                u32 a[2][4], bf[4][4];
                ldsm4(a[0], aoff + aRow[0] + (ak ^ aXor[0]));
                ldsm4(a[1], aoff + aRow[1] + (ak ^ aXor[1]));
#pragma unroll
                for (int p = 0; p < 4; ++p)
                    ldsm4(bf[p], boff + bRow[p] + (bk ^ bXor[p]));
#pragma unroll
                for (int mt = 0; mt < 2; ++mt)
#pragma unroll
                    for (int j = 0; j < 8; ++j)
                        mma16816(acc[mt][j], a[mt],
                                 bf[j >> 1][(j & 1) * 2], bf[j >> 1][(j & 1) * 2 + 1]);
            }
        }
        __syncthreads();
    }

    // ---------------- epilogue ----------------
    const int baseN = wn * 64 + 2 * (lane & 3);
#pragma unroll
    for (int mt = 0; mt < 2; ++mt) {
#pragma unroll
        for (int h = 0; h < 2; ++h) {
            int m = wm * 32 + mt * 16 + (lane >> 2) + h * 8;
            if (MODE == 0) {
                size_t gi = ((size_t)(b * 128 + y0) * 128 + m) * 256;
#pragma unroll
                for (int j = 0; j < 8; ++j) {
                    int n = baseN + j * 8;
                    float r0 = acc[mt][j][h * 2]     * dmod[b * 256 + n]     + bnoise[n];
                    float r1 = acc[mt][j][h * 2 + 1] * dmod[b * 256 + n + 1] + bnoise[n + 1];
                    r0 = (r0 >= 0.0f) ? r0 : 0.2f * r0;
                    r1 = (r1 >= 0.0f) ? r1 : 0.2f * r1;
                    u32 h0, l0, h1, l1;
                    bsplit(r0, h0, l0);
                    bsplit(r1, h1, l1);
                    *(u32*)(g_y1h + gi + n) = h0 | (h1 << 16);
                    *(u32*)(g_y1l + gi + n) = l0 | (l1 << 16);
                }
            } else {
#pragma unroll
                for (int j = 0; j < 8; ++j) {
                    int n = baseN + j * 8;
                    float r0 = acc[mt][j][h * 2]     * dmod[b * 256 + n]     + bnoise[n];
                    float r1 = acc[mt][j][h * 2 + 1] * dmod[b * 256 + n + 1] + bnoise[n + 1];
                    r0 = (r0 >= 0.0f) ? r0 : 0.2f * r0;
                    r1 = (r1 >= 0.0f) ? r1 : 0.2f * r1;
                    outp[((size_t)(b * 256 + n)     * 128 + y0) * 128 + m] = r0;
                    outp[((size_t)(b * 256 + n + 1) * 128 + y0) * 128 + m] = r1;
                }
            }
        }
    }
}

// ---------------- launch ----------------
extern "C" void kernel_launch(void* const* d_in, const int* in_sizes, int n_in,
                              void* d_out, int out_size) {
    (void)in_sizes; (void)n_in; (void)out_size;
    const float* x         = (const float*)d_in[0];
    const float* istyle    = (const float*)d_in[1];
    const float* w_style1  = (const float*)d_in[2];
    const float* b_style1  = (const float*)d_in[3];
    const float* w_style2  = (const float*)d_in[4];
    const float* b_style2  = (const float*)d_in[5];
    const float* b_noise1  = (const float*)d_in[7];
    const float* b_noise2  = (const float*)d_in[9];
    const float* conv1_w   = (const float*)d_in[10];
    const float* conv2_w   = (const float*)d_in[11];
    const float* conv1x1_w = (const float*)d_in[12];
    float* out = (float*)d_out;

    cudaFuncSetAttribute(k_convhmma<0>, cudaFuncAttributeMaxDynamicSharedMemorySize, SMEM_BYTES);
    cudaFuncSetAttribute(k_convhmma<1>, cudaFuncAttributeMaxDynamicSharedMemorySize, SMEM_BYTES);

    k_transpose<<<dim3(256, 16), 256>>>(x);
    k_upsplit<<<65536, 256>>>();
    k_styles<<<8, 256>>>(istyle, w_style1, b_style1, w_style2, b_style2);
    k_wsq<<<dim3(256, 2), 256>>>(conv1_w, conv2_w);
    k_demod<<<dim3(256, 4, 2), 256>>>();
    k_prepw1<<<dim3(36, 256), 256>>>(conv1_w);
    k_prepw2<<<dim3(40, 256), 256>>>(conv2_w, conv1x1_w);
    k_convhmma<0><<<dim3(128, 4), 512, SMEM_BYTES>>>(b_noise1, nullptr);
    k_convhmma<1><<<dim3(128, 4), 512, SMEM_BYTES>>>(b_noise2, out);
}

// round 7
// speedup vs baseline: 3.2589x; 1.3694x over previous
#include <cuda_runtime.h>
#include <cuda_bf16.h>
#include <cstdint>

typedef unsigned long long u64;
typedef unsigned int u32;

// ---------------- problem constants ----------------
constexpr int NB = 4, NC = 256, NO = 256;
constexpr int IH = 64, IW = 64, OH = 128, OW = 128;
constexpr size_t NELEM = (size_t)NB * NC * OH * OW;   // 16,777,216

constexpr u32 SMEM_BYTES = 2 * 98304;                 // 2 stage buffers (A 32KB + B 64KB)

// ---------------- device scratch ----------------
__device__ float g_xt[(size_t)NB * IH * IW * NC];                    // NHWC fp32 (64x64)
__device__ __align__(128) __nv_bfloat16 g_xh[NELEM], g_xl[NELEM];    // NHWC split of upsampled x
__device__ __align__(128) __nv_bfloat16 g_y1h[NELEM], g_y1l[NELEM];  // NHWC split of y1
__device__ __align__(128) __nv_bfloat16 g_B1h[4 * 9 * 256 * 256],  g_B1l[4 * 9 * 256 * 256];
__device__ __align__(128) __nv_bfloat16 g_B2h[4 * 10 * 256 * 256], g_B2l[4 * 10 * 256 * 256];
__device__ float g_s1[NB * NC], g_s2[NB * NC];
__device__ float g_d1[NB * NO], g_d2[NB * NO];
__device__ float g_wsq1[NO * NC], g_wsq2[NO * NC];

// ---------------- helpers ----------------
__device__ __forceinline__ u32 smem_u32(const void* p) {
    u32 a;
    asm("{ .reg .u64 t; cvta.to.shared.u64 t, %1; cvt.u32.u64 %0, t; }" : "=r"(a) : "l"(p));
    return a;
}
__device__ __forceinline__ void ldsm4(u32* r, u32 addr) {
    asm volatile("ldmatrix.sync.aligned.m8n8.x4.shared.b16 {%0,%1,%2,%3}, [%4];"
                 : "=r"(r[0]), "=r"(r[1]), "=r"(r[2]), "=r"(r[3]) : "r"(addr));
}
__device__ __forceinline__ void mma16816(float* d, const u32* a, u32 b0, u32 b1) {
    asm volatile("mma.sync.aligned.m16n8k16.row.col.f32.bf16.bf16.f32 "
                 "{%0,%1,%2,%3}, {%4,%5,%6,%7}, {%8,%9}, {%0,%1,%2,%3};"
                 : "+f"(d[0]), "+f"(d[1]), "+f"(d[2]), "+f"(d[3])
                 : "r"(a[0]), "r"(a[1]), "r"(a[2]), "r"(a[3]), "r"(b0), "r"(b1));
}
__device__ __forceinline__ void cp16(u32 dst, const void* src, u32 sz) {
    asm volatile("cp.async.cg.shared.global [%0], [%1], 16, %2;"
                 :: "r"(dst), "l"(src), "r"(sz) : "memory");
}
__device__ __forceinline__ u32 swz(u32 off) { return off ^ ((off >> 3) & 0x70); }

__device__ __forceinline__ void bsplit(float v, u32& hbits, u32& lbits) {
    __nv_bfloat16 h = __float2bfloat16(v);
    hbits = (u32)__bfloat16_as_ushort(h);
    lbits = (u32)__bfloat16_as_ushort(__float2bfloat16(v - __bfloat162float(h)));
}

// ---------------- 1) NCHW -> NHWC fp32 transpose (64x64) ----------------
__global__ void k_transpose(const float* __restrict__ x) {
    __shared__ float tile[32][33];
    int by = blockIdx.x;                 // b*64 + y
    int b = by >> 6, y = by & 63;
    int cblk = (blockIdx.y >> 1) * 32, xblk = (blockIdx.y & 1) * 32;
    int t = threadIdx.x;
    int ci = t >> 5, xi = t & 31;
#pragma unroll
    for (int p = 0; p < 4; ++p) {
        int c = cblk + p * 8 + ci;
        tile[p * 8 + ci][xi] = x[((size_t)(b * 256 + c) * 64 + y) * 64 + xblk + xi];
    }
    __syncthreads();
    int xi2 = t >> 5, c2 = t & 31;
#pragma unroll
    for (int p = 0; p < 4; ++p) {
        int xx = xblk + p * 8 + xi2;
        g_xt[((size_t)(b * 64 + y) * 64 + xx) * 256 + cblk + c2] = tile[c2][p * 8 + xi2];
    }
}

// ---------------- 2) bilinear 2x upsample + bf16 split (NHWC) ----------------
__global__ void k_upsplit() {
    int i = blockIdx.x * 256 + threadIdx.x;     // 16,777,216
    int c  = i & 255;
    int xo = (i >> 8) & 127;
    int yo = (i >> 15) & 127;
    int b  = i >> 22;

    int y0, x0; float fy, fx;
    if (yo & 1) { y0 = yo >> 1;       fy = 0.25f; }
    else        { y0 = (yo >> 1) - 1; fy = 0.75f; }
    if (xo & 1) { x0 = xo >> 1;       fx = 0.25f; }
    else        { x0 = (xo >> 1) - 1; fx = 0.75f; }
    int y1i = min(y0 + 1, IH - 1); y0 = max(y0, 0);
    int x1i = min(x0 + 1, IW - 1); x0 = max(x0, 0);

    const float* base = g_xt + (size_t)b * IH * IW * 256 + c;
    float v00 = base[(y0  * 64 + x0 ) * 256], v01 = base[(y0  * 64 + x1i) * 256];
    float v10 = base[(y1i * 64 + x0 ) * 256], v11 = base[(y1i * 64 + x1i) * 256];
    float vt = v00 + fx * (v01 - v00);
    float vb = v10 + fx * (v11 - v10);
    float v = vt + fy * (vb - vt);

    __nv_bfloat16 h = __float2bfloat16(v);
    g_xh[i] = h;
    g_xl[i] = __float2bfloat16(v - __bfloat162float(h));
}

// ---------------- 3) styles ----------------
__global__ void k_styles(const float* __restrict__ istyle,
                         const float* __restrict__ w1, const float* __restrict__ b1,
                         const float* __restrict__ w2, const float* __restrict__ b2) {
    int b = blockIdx.x & 3;
    int which = blockIdx.x >> 2;
    int c = threadIdx.x;
    const float* wrow = (which ? w2 : w1) + (size_t)c * 256;
    const float* ist = istyle + b * 256;
    float acc = (which ? b2 : b1)[c];
#pragma unroll 8
    for (int k = 0; k < 256; ++k) acc += ist[k] * wrow[k];
    (which ? g_s2 : g_s1)[b * 256 + c] = acc + 1.0f;
}

// ---------------- 4) wsq ----------------
__global__ void k_wsq(const float* __restrict__ w1, const float* __restrict__ w2) {
    int which = blockIdx.y;
    int i = blockIdx.x * 256 + threadIdx.x;
    const float* w = (which ? w2 : w1) + (size_t)i * 9;
    float s = 0.0f;
#pragma unroll
    for (int k = 0; k < 9; ++k) { float v = w[k]; s += v * v; }
    (which ? g_wsq2 : g_wsq1)[i] = s;
}

// ---------------- 5) demod ----------------
__global__ void k_demod() {
    int o = blockIdx.x, b = blockIdx.y, which = blockIdx.z;
    int c = threadIdx.x;
    const float* wsq = which ? g_wsq2 : g_wsq1;
    const float* s   = which ? g_s2  : g_s1;
    float sv = s[b * NC + c];
    float v = wsq[o * NC + c] * sv * sv;
    __shared__ float red[256];
    red[c] = v;
    __syncthreads();
    for (int st = 128; st; st >>= 1) {
        if (c < st) red[c] += red[c + st];
        __syncthreads();
    }
    if (c == 0) (which ? g_d2 : g_d1)[b * NO + o] = rsqrtf(red[0] + 1e-8f);
}

// ---------------- 6) weight prep: B[b,tap,oc,c] = W[oc,c,tap]*s[b,c], split ----------------
__global__ void k_prepw1(const float* __restrict__ w1) {
    int bt = blockIdx.x;            // b*9+tap
    int b = bt / 9, tap = bt % 9;
    int oc = blockIdx.y, c = threadIdx.x;
    float v = w1[((size_t)oc * 256 + c) * 9 + tap] * g_s1[b * 256 + c];
    __nv_bfloat16 h = __float2bfloat16(v);
    size_t o = ((size_t)bt * 256 + oc) * 256 + c;
    g_B1h[o] = h;
    g_B1l[o] = __float2bfloat16(v - __bfloat162float(h));
}
__global__ void k_prepw2(const float* __restrict__ w2, const float* __restrict__ w1x1) {
    int bt = blockIdx.x;            // b*10+tap
    int b = bt / 10, tap = bt % 10;
    int oc = blockIdx.y, c = threadIdx.x;
    float v;
    if (tap < 9) v = w2[((size_t)oc * 256 + c) * 9 + tap] * g_s2[b * 256 + c];
    else         v = w1x1[(size_t)oc * 256 + c] * (1.0f / g_d2[b * 256 + oc]);
    __nv_bfloat16 h = __float2bfloat16(v);
    size_t o = ((size_t)bt * 256 + oc) * 256 + c;
    g_B2h[o] = h;
    g_B2l[o] = __float2bfloat16(v - __bfloat162float(h));
}

// ---------------- 7) warp-MMA implicit-GEMM modulated conv ----------------
// MODE 0: A = xh/xl (9 taps), epilogue -> y1 split NHWC.
// MODE 1: A = y1h/y1l (taps 0-8) + xh/xl (tap 9 = folded 1x1 skip), epilogue -> out NCHW fp32.
// Per CTA: M=128 pixels (row y0) x N=256 oc. 8 warps (2M x 4N), warp tile m64 x n64.
// Fused 3-pass split: per k-step load Ah/Al frags once, stream Bh/Bl, issue hh+hl+lh MMAs.
// Stage buffer layout (98304 B): Ah @0 (16KB), Al @16384, Bh @32768 (32KB), Bl @65536.
template <int MODE>
__global__ void __launch_bounds__(256, 1) k_convhmma(const float* __restrict__ bnoise,
                                                     float* __restrict__ outp) {
    constexpr int NT = (MODE == 0) ? 9 : 10;
    constexpr int S = NT * 4;
    extern __shared__ __align__(1024) char smem[];
    const u32 sb = smem_u32(smem);
    const int t = threadIdx.x;
    const int y0 = blockIdx.x, b = blockIdx.y;
    const float* dmod = (MODE == 0) ? g_d1 : g_d2;

    const int warp = t >> 5, lane = t & 31;
    const int wm = warp & 1, wn = warp >> 1;      // 2 m-tiles x 4 n-tiles of 64
    const int li = lane >> 3, lr = lane & 7;

    // ldmatrix addressing: addr = tile + row*128 + ((colbyte + kadd) ^ ((row&7)*16))
    u32 aRow[4], aXor[4];
#pragma unroll
    for (int mt = 0; mt < 4; ++mt) {
        int row = wm * 64 + mt * 16 + lr + ((li & 1) << 3);
        aRow[mt] = (u32)row << 7;
        aXor[mt] = ((u32)row & 7u) << 4;
    }
    const u32 aCol = ((u32)li >> 1) << 4;
    u32 bRow[4], bXor[4];
#pragma unroll
    for (int p = 0; p < 4; ++p) {
        int row = wn * 64 + p * 16 + lr + ((li >> 1) << 3);
        bRow[p] = (u32)row << 7;
        bXor[p] = ((u32)row & 7u) << 4;
    }
    const u32 bCol = ((u32)li & 1u) << 4;

    float acc[4][8][4];
#pragma unroll
    for (int mt = 0; mt < 4; ++mt)
#pragma unroll
        for (int j = 0; j < 8; ++j)
#pragma unroll
            for (int q = 0; q < 4; ++q) acc[mt][j][q] = 0.0f;

    auto load_stage = [&](int s) {
        int tap = s >> 2, c0 = (s & 3) << 6;
        u32 base = sb + (u32)(s & 1) * 98304u;
        const __nv_bfloat16 *Ah, *Al;
        int dy, dx;
        if (MODE == 1 && tap == 9) { Ah = g_xh; Al = g_xl; dy = 0; dx = 0; }
        else {
            dy = tap / 3 - 1; dx = tap % 3 - 1;
            if (MODE == 0) { Ah = g_xh; Al = g_xl; } else { Ah = g_y1h; Al = g_y1l; }
        }
        int y = y0 + dy;
        bool yok = ((unsigned)y < 128u);
        int yc = min(max(y, 0), 127);
        // A tiles: [128 m][64 c] bf16, h and l  (2048 vec16 / 256 thr = 8)
#pragma unroll
        for (int i = 0; i < 8; ++i) {
            int u = t + i * 256;
            int split = u >> 10, rem = u & 1023;
            int m = rem >> 3, j = rem & 7;
            int xx = m + dx;
            bool ok = yok && ((unsigned)xx < 128u);
            int xc = min(max(xx, 0), 127);
            const __nv_bfloat16* src = (split ? Al : Ah)
                + ((size_t)((b * 128 + yc) * 128 + xc) * 256 + c0 + j * 8);
            u32 dst = base + (u32)split * 16384u + swz(((u32)m << 7) + ((u32)j << 4));
            cp16(dst, src, ok ? 16u : 0u);
        }
        // B tiles: [256 oc][64 c] bf16, h and l  (4096 vec16 / 256 thr = 16)
        const __nv_bfloat16* Bh = (MODE == 0) ? g_B1h : g_B2h;
        const __nv_bfloat16* Bl = (MODE == 0) ? g_B1l : g_B2l;
        size_t btbase = (size_t)(b * NT + tap) * 65536 + c0;
#pragma unroll
        for (int i = 0; i < 16; ++i) {
            int u = t + i * 256;
            int split = u >> 11, rem = u & 2047;
            int n = rem >> 3, j = rem & 7;
            const __nv_bfloat16* src = (split ? Bl : Bh) + (btbase + n * 256 + j * 8);
            u32 dst = base + 32768u + (u32)split * 32768u + swz(((u32)n << 7) + ((u32)j << 4));
            cp16(dst, src, 16u);
        }
        asm volatile("cp.async.commit_group;" ::: "memory");
    };

    load_stage(0);
    for (int s = 0; s < S; ++s) {
        if (s + 1 < S) {
            load_stage(s + 1);
            asm volatile("cp.async.wait_group 1;" ::: "memory");
        } else {
            asm volatile("cp.async.wait_group 0;" ::: "memory");
        }
        __syncthreads();
        u32 base = sb + (u32)(s & 1) * 98304u;
        const u32 aoff_h = base, aoff_l = base + 16384u;
        const u32 boff_h = base + 32768u, boff_l = base + 65536u;
#pragma unroll
        for (int kk = 0; kk < 4; ++kk) {
            u32 kadd = (u32)kk << 5;
            u32 ak = aCol + kadd;
            u32 bk = bCol + kadd;
            u32 ah[4][4], al[4][4];
#pragma unroll
            for (int mt = 0; mt < 4; ++mt) {
                ldsm4(ah[mt], aoff_h + aRow[mt] + (ak ^ aXor[mt]));
                ldsm4(al[mt], aoff_l + aRow[mt] + (ak ^ aXor[mt]));
            }
#pragma unroll
            for (int p = 0; p < 4; ++p) {
                u32 bh[4], bl[4];
                ldsm4(bh, boff_h + bRow[p] + (bk ^ bXor[p]));
                ldsm4(bl, boff_l + bRow[p] + (bk ^ bXor[p]));
                // hh
#pragma unroll
                for (int mt = 0; mt < 4; ++mt) {
                    mma16816(acc[mt][2 * p],     ah[mt], bh[0], bh[1]);
                    mma16816(acc[mt][2 * p + 1], ah[mt], bh[2], bh[3]);
                }
                // hl
#pragma unroll
                for (int mt = 0; mt < 4; ++mt) {
                    mma16816(acc[mt][2 * p],     ah[mt], bl[0], bl[1]);
                    mma16816(acc[mt][2 * p + 1], ah[mt], bl[2], bl[3]);
                }
                // lh
#pragma unroll
                for (int mt = 0; mt < 4; ++mt) {
                    mma16816(acc[mt][2 * p],     al[mt], bh[0], bh[1]);
                    mma16816(acc[mt][2 * p + 1], al[mt], bh[2], bh[3]);
                }
            }
        }
        __syncthreads();
    }

    // ---------------- epilogue ----------------
    const int baseN = wn * 64 + 2 * (lane & 3);
#pragma unroll
    for (int mt = 0; mt < 4; ++mt) {
#pragma unroll
        for (int h = 0; h < 2; ++h) {
            int m = wm * 64 + mt * 16 + (lane >> 2) + h * 8;
            if (MODE == 0) {
                size_t gi = ((size_t)(b * 128 + y0) * 128 + m) * 256;
#pragma unroll
                for (int j = 0; j < 8; ++j) {
                    int n = baseN + j * 8;
                    float r0 = acc[mt][j][h * 2]     * dmod[b * 256 + n]     + bnoise[n];
                    float r1 = acc[mt][j][h * 2 + 1] * dmod[b * 256 + n + 1] + bnoise[n + 1];
                    r0 = (r0 >= 0.0f) ? r0 : 0.2f * r0;
                    r1 = (r1 >= 0.0f) ? r1 : 0.2f * r1;
                    u32 h0, l0, h1, l1;
                    bsplit(r0, h0, l0);
                    bsplit(r1, h1, l1);
                    *(u32*)(g_y1h + gi + n) = h0 | (h1 << 16);
                    *(u32*)(g_y1l + gi + n) = l0 | (l1 << 16);
                }
            } else {
#pragma unroll
                for (int j = 0; j < 8; ++j) {
                    int n = baseN + j * 8;
                    float r0 = acc[mt][j][h * 2]     * dmod[b * 256 + n]     + bnoise[n];
                    float r1 = acc[mt][j][h * 2 + 1] * dmod[b * 256 + n + 1] + bnoise[n + 1];
                    r0 = (r0 >= 0.0f) ? r0 : 0.2f * r0;
                    r1 = (r1 >= 0.0f) ? r1 : 0.2f * r1;
                    outp[((size_t)(b * 256 + n)     * 128 + y0) * 128 + m] = r0;
                    outp[((size_t)(b * 256 + n + 1) * 128 + y0) * 128 + m] = r1;
                }
            }
        }
    }
}

// ---------------- launch ----------------
extern "C" void kernel_launch(void* const* d_in, const int* in_sizes, int n_in,
                              void* d_out, int out_size) {
    (void)in_sizes; (void)n_in; (void)out_size;
    const float* x         = (const float*)d_in[0];
    const float* istyle    = (const float*)d_in[1];
    const float* w_style1  = (const float*)d_in[2];
    const float* b_style1  = (const float*)d_in[3];
    const float* w_style2  = (const float*)d_in[4];
    const float* b_style2  = (const float*)d_in[5];
    const float* b_noise1  = (const float*)d_in[7];
    const float* b_noise2  = (const float*)d_in[9];
    const float* conv1_w   = (const float*)d_in[10];
    const float* conv2_w   = (const float*)d_in[11];
    const float* conv1x1_w = (const float*)d_in[12];
    float* out = (float*)d_out;

    cudaFuncSetAttribute(k_convhmma<0>, cudaFuncAttributeMaxDynamicSharedMemorySize, SMEM_BYTES);
    cudaFuncSetAttribute(k_convhmma<1>, cudaFuncAttributeMaxDynamicSharedMemorySize, SMEM_BYTES);

    k_transpose<<<dim3(256, 16), 256>>>(x);
    k_upsplit<<<65536, 256>>>();
    k_styles<<<8, 256>>>(istyle, w_style1, b_style1, w_style2, b_style2);
    k_wsq<<<dim3(256, 2), 256>>>(conv1_w, conv2_w);
    k_demod<<<dim3(256, 4, 2), 256>>>();
    k_prepw1<<<dim3(36, 256), 256>>>(conv1_w);
    k_prepw2<<<dim3(40, 256), 256>>>(conv2_w, conv1x1_w);
    k_convhmma<0><<<dim3(128, 4), 256, SMEM_BYTES>>>(b_noise1, nullptr);
    k_convhmma<1><<<dim3(128, 4), 256, SMEM_BYTES>>>(b_noise2, out);
}

// round 8
// speedup vs baseline: 4.4828x; 1.3756x over previous
#include <cuda_runtime.h>
#include <cuda_fp16.h>
#include <cstdint>

typedef unsigned long long u64;
typedef unsigned int u32;

// ---------------- problem constants ----------------
constexpr int NB = 4, NC = 256, NO = 256;
constexpr int IH = 64, IW = 64, OH = 128, OW = 128;
constexpr size_t NELEM = (size_t)NB * NC * OH * OW;   // 16,777,216

// Stage buffer: Ah 16KB @0, Al 16KB @16384, Bh 32KB @32768 -> 64KB; double buffered.
constexpr u32 SMEM_BYTES = 2 * 65536;

// ---------------- device scratch ----------------
__device__ float g_xt[(size_t)NB * IH * IW * NC];            // NHWC fp32 (64x64)
__device__ __align__(128) __half g_xh[NELEM], g_xl[NELEM];   // NHWC fp16 split of upsampled x
__device__ __align__(128) __half g_y1h[NELEM], g_y1l[NELEM]; // NHWC fp16 split of y1
__device__ __align__(128) __half g_B1h[4 * 9 * 256 * 256];   // [b*9+tap][oc][c]  (fp16, high only)
__device__ __align__(128) __half g_B2h[4 * 10 * 256 * 256];  // [b*10+tap][oc][c]
__device__ float g_s1[NB * NC], g_s2[NB * NC];
__device__ float g_d1[NB * NO], g_d2[NB * NO];
__device__ float g_wsq1[NO * NC], g_wsq2[NO * NC];

// ---------------- helpers ----------------
__device__ __forceinline__ u32 smem_u32(const void* p) {
    u32 a;
    asm("{ .reg .u64 t; cvta.to.shared.u64 t, %1; cvt.u32.u64 %0, t; }" : "=r"(a) : "l"(p));
    return a;
}
__device__ __forceinline__ void ldsm4(u32* r, u32 addr) {
    asm volatile("ldmatrix.sync.aligned.m8n8.x4.shared.b16 {%0,%1,%2,%3}, [%4];"
                 : "=r"(r[0]), "=r"(r[1]), "=r"(r[2]), "=r"(r[3]) : "r"(addr));
}
__device__ __forceinline__ void mma16816(float* d, const u32* a, u32 b0, u32 b1) {
    asm volatile("mma.sync.aligned.m16n8k16.row.col.f32.f16.f16.f32 "
                 "{%0,%1,%2,%3}, {%4,%5,%6,%7}, {%8,%9}, {%0,%1,%2,%3};"
                 : "+f"(d[0]), "+f"(d[1]), "+f"(d[2]), "+f"(d[3])
                 : "r"(a[0]), "r"(a[1]), "r"(a[2]), "r"(a[3]), "r"(b0), "r"(b1));
}
__device__ __forceinline__ void cp16(u32 dst, const void* src, u32 sz) {
    asm volatile("cp.async.cg.shared.global [%0], [%1], 16, %2;"
                 :: "r"(dst), "l"(src), "r"(sz) : "memory");
}
__device__ __forceinline__ u32 swz(u32 off) { return off ^ ((off >> 3) & 0x70); }

__device__ __forceinline__ void hsplit(float v, u32& hbits, u32& lbits) {
    __half h = __float2half(v);
    hbits = (u32)__half_as_ushort(h);
    lbits = (u32)__half_as_ushort(__float2half(v - __half2float(h)));
}

// ---------------- 1) NCHW -> NHWC fp32 transpose (64x64) ----------------
__global__ void k_transpose(const float* __restrict__ x) {
    __shared__ float tile[32][33];
    int by = blockIdx.x;                 // b*64 + y
    int b = by >> 6, y = by & 63;
    int cblk = (blockIdx.y >> 1) * 32, xblk = (blockIdx.y & 1) * 32;
    int t = threadIdx.x;
    int ci = t >> 5, xi = t & 31;
#pragma unroll
    for (int p = 0; p < 4; ++p) {
        int c = cblk + p * 8 + ci;
        tile[p * 8 + ci][xi] = x[((size_t)(b * 256 + c) * 64 + y) * 64 + xblk + xi];
    }
    __syncthreads();
    int xi2 = t >> 5, c2 = t & 31;
#pragma unroll
    for (int p = 0; p < 4; ++p) {
        int xx = xblk + p * 8 + xi2;
        g_xt[((size_t)(b * 64 + y) * 64 + xx) * 256 + cblk + c2] = tile[c2][p * 8 + xi2];
    }
}

// ---------------- 2) bilinear 2x upsample + fp16 split (NHWC) ----------------
__global__ void k_upsplit() {
    int i = blockIdx.x * 256 + threadIdx.x;     // 16,777,216
    int c  = i & 255;
    int xo = (i >> 8) & 127;
    int yo = (i >> 15) & 127;
    int b  = i >> 22;

    int y0, x0; float fy, fx;
    if (yo & 1) { y0 = yo >> 1;       fy = 0.25f; }
    else        { y0 = (yo >> 1) - 1; fy = 0.75f; }
    if (xo & 1) { x0 = xo >> 1;       fx = 0.25f; }
    else        { x0 = (xo >> 1) - 1; fx = 0.75f; }
    int y1i = min(y0 + 1, IH - 1); y0 = max(y0, 0);
    int x1i = min(x0 + 1, IW - 1); x0 = max(x0, 0);

    const float* base = g_xt + (size_t)b * IH * IW * 256 + c;
    float v00 = base[(y0  * 64 + x0 ) * 256], v01 = base[(y0  * 64 + x1i) * 256];
    float v10 = base[(y1i * 64 + x0 ) * 256], v11 = base[(y1i * 64 + x1i) * 256];
    float vt = v00 + fx * (v01 - v00);
    float vb = v10 + fx * (v11 - v10);
    float v = vt + fy * (vb - vt);

    __half h = __float2half(v);
    g_xh[i] = h;
    g_xl[i] = __float2half(v - __half2float(h));
}

// ---------------- 3) styles ----------------
__global__ void k_styles(const float* __restrict__ istyle,
                         const float* __restrict__ w1, const float* __restrict__ b1,
                         const float* __restrict__ w2, const float* __restrict__ b2) {
    int b = blockIdx.x & 3;
    int which = blockIdx.x >> 2;
    int c = threadIdx.x;
    const float* wrow = (which ? w2 : w1) + (size_t)c * 256;
    const float* ist = istyle + b * 256;
    float acc = (which ? b2 : b1)[c];
#pragma unroll 8
    for (int k = 0; k < 256; ++k) acc += ist[k] * wrow[k];
    (which ? g_s2 : g_s1)[b * 256 + c] = acc + 1.0f;
}

// ---------------- 4) wsq ----------------
__global__ void k_wsq(const float* __restrict__ w1, const float* __restrict__ w2) {
    int which = blockIdx.y;
    int i = blockIdx.x * 256 + threadIdx.x;
    const float* w = (which ? w2 : w1) + (size_t)i * 9;
    float s = 0.0f;
#pragma unroll
    for (int k = 0; k < 9; ++k) { float v = w[k]; s += v * v; }
    (which ? g_wsq2 : g_wsq1)[i] = s;
}

// ---------------- 5) demod ----------------
__global__ void k_demod() {
    int o = blockIdx.x, b = blockIdx.y, which = blockIdx.z;
    int c = threadIdx.x;
    const float* wsq = which ? g_wsq2 : g_wsq1;
    const float* s   = which ? g_s2  : g_s1;
    float sv = s[b * NC + c];
    float v = wsq[o * NC + c] * sv * sv;
    __shared__ float red[256];
    red[c] = v;
    __syncthreads();
    for (int st = 128; st; st >>= 1) {
        if (c < st) red[c] += red[c + st];
        __syncthreads();
    }
    if (c == 0) (which ? g_d2 : g_d1)[b * NO + o] = rsqrtf(red[0] + 1e-8f);
}

// ---------------- 6) weight prep: B[b,tap,oc,c] = W[oc,c,tap]*s[b,c] (fp16 high) ----------------
__global__ void k_prepw1(const float* __restrict__ w1) {
    int bt = blockIdx.x;            // b*9+tap
    int b = bt / 9, tap = bt % 9;
    int oc = blockIdx.y, c = threadIdx.x;
    float v = w1[((size_t)oc * 256 + c) * 9 + tap] * g_s1[b * 256 + c];
    g_B1h[((size_t)bt * 256 + oc) * 256 + c] = __float2half(v);
}
__global__ void k_prepw2(const float* __restrict__ w2, const float* __restrict__ w1x1) {
    int bt = blockIdx.x;            // b*10+tap
    int b = bt / 10, tap = bt % 10;
    int oc = blockIdx.y, c = threadIdx.x;
    float v;
    if (tap < 9) v = w2[((size_t)oc * 256 + c) * 9 + tap] * g_s2[b * 256 + c];
    else         v = w1x1[(size_t)oc * 256 + c] * (1.0f / g_d2[b * 256 + oc]);
    g_B2h[((size_t)bt * 256 + oc) * 256 + c] = __float2half(v);
}

// ---------------- 7) warp-MMA implicit-GEMM modulated conv (fp16 2-pass split) ----------------
// y ~= (Ah + Al) . Bh   (A split exact to 2^-22; dropped term x*wl ~ 2^-11.5 noise)
// MODE 0: A = xh/xl (9 taps), epilogue -> y1 split NHWC fp16.
// MODE 1: A = y1h/y1l (taps 0-8) + xh/xl (tap 9 = folded 1x1 skip), epilogue -> out NCHW fp32.
// Per CTA: M=128 pixels (row y0) x N=256 oc. 8 warps (2M x 4N), warp tile m64 x n64.
template <int MODE>
__global__ void __launch_bounds__(256, 1) k_convhmma(const float* __restrict__ bnoise,
                                                     float* __restrict__ outp) {
    constexpr int NT = (MODE == 0) ? 9 : 10;
    constexpr int S = NT * 4;
    extern __shared__ __align__(1024) char smem[];
    const u32 sb = smem_u32(smem);
    const int t = threadIdx.x;
    const int y0 = blockIdx.x, b = blockIdx.y;
    const float* dmod = (MODE == 0) ? g_d1 : g_d2;

    const int warp = t >> 5, lane = t & 31;
    const int wm = warp & 1, wn = warp >> 1;      // 2 m-tiles x 4 n-tiles of 64
    const int li = lane >> 3, lr = lane & 7;

    // ldmatrix addressing: addr = tile + row*128 + ((colbyte + kadd) ^ ((row&7)*16))
    u32 aRow[4], aXor[4];
#pragma unroll
    for (int mt = 0; mt < 4; ++mt) {
        int row = wm * 64 + mt * 16 + lr + ((li & 1) << 3);
        aRow[mt] = (u32)row << 7;
        aXor[mt] = ((u32)row & 7u) << 4;
    }
    const u32 aCol = ((u32)li >> 1) << 4;
    u32 bRow[4], bXor[4];
#pragma unroll
    for (int p = 0; p < 4; ++p) {
        int row = wn * 64 + p * 16 + lr + ((li >> 1) << 3);
        bRow[p] = (u32)row << 7;
        bXor[p] = ((u32)row & 7u) << 4;
    }
    const u32 bCol = ((u32)li & 1u) << 4;

    float acc[4][8][4];
#pragma unroll
    for (int mt = 0; mt < 4; ++mt)
#pragma unroll
        for (int j = 0; j < 8; ++j)
#pragma unroll
            for (int q = 0; q < 4; ++q) acc[mt][j][q] = 0.0f;

    auto load_stage = [&](int s) {
        int tap = s >> 2, c0 = (s & 3) << 6;
        u32 base = sb + (u32)(s & 1) * 65536u;
        const __half *Ah, *Al;
        int dy, dx;
        if (MODE == 1 && tap == 9) { Ah = g_xh; Al = g_xl; dy = 0; dx = 0; }
        else {
            dy = tap / 3 - 1; dx = tap % 3 - 1;
            if (MODE == 0) { Ah = g_xh; Al = g_xl; } else { Ah = g_y1h; Al = g_y1l; }
        }
        int y = y0 + dy;
        bool yok = ((unsigned)y < 128u);
        int yc = min(max(y, 0), 127);
        // A tiles: [128 m][64 c] fp16, h and l  (2048 vec16 / 256 thr = 8)
#pragma unroll
        for (int i = 0; i < 8; ++i) {
            int u = t + i * 256;
            int split = u >> 10, rem = u & 1023;
            int m = rem >> 3, j = rem & 7;
            int xx = m + dx;
            bool ok = yok && ((unsigned)xx < 128u);
            int xc = min(max(xx, 0), 127);
            const __half* src = (split ? Al : Ah)
                + ((size_t)((b * 128 + yc) * 128 + xc) * 256 + c0 + j * 8);
            u32 dst = base + (u32)split * 16384u + swz(((u32)m << 7) + ((u32)j << 4));
            cp16(dst, src, ok ? 16u : 0u);
        }
        // B tile: [256 oc][64 c] fp16, high only  (2048 vec16 / 256 thr = 8)
        const __half* Bh = (MODE == 0) ? g_B1h : g_B2h;
        size_t btbase = (size_t)(b * NT + tap) * 65536 + c0;
#pragma unroll
        for (int i = 0; i < 8; ++i) {
            int u = t + i * 256;
            int n = u >> 3, j = u & 7;
            const __half* src = Bh + (btbase + n * 256 + j * 8);
            u32 dst = base + 32768u + swz(((u32)n << 7) + ((u32)j << 4));
            cp16(dst, src, 16u);
        }
        asm volatile("cp.async.commit_group;" ::: "memory");
    };

    load_stage(0);
    for (int s = 0; s < S; ++s) {
        if (s + 1 < S) {
            load_stage(s + 1);
            asm volatile("cp.async.wait_group 1;" ::: "memory");
        } else {
            asm volatile("cp.async.wait_group 0;" ::: "memory");
        }
        __syncthreads();
        u32 base = sb + (u32)(s & 1) * 65536u;
        const u32 aoff_h = base, aoff_l = base + 16384u;
        const u32 boff_h = base + 32768u;
#pragma unroll
        for (int kk = 0; kk < 4; ++kk) {
            u32 kadd = (u32)kk << 5;
            u32 ak = aCol + kadd;
            u32 bk = bCol + kadd;
            u32 ah[4][4], al[4][4];
#pragma unroll
            for (int mt = 0; mt < 4; ++mt) {
                ldsm4(ah[mt], aoff_h + aRow[mt] + (ak ^ aXor[mt]));
                ldsm4(al[mt], aoff_l + aRow[mt] + (ak ^ aXor[mt]));
            }
#pragma unroll
            for (int p = 0; p < 4; ++p) {
                u32 bh[4];
                ldsm4(bh, boff_h + bRow[p] + (bk ^ bXor[p]));
                // hh
#pragma unroll
                for (int mt = 0; mt < 4; ++mt) {
                    mma16816(acc[mt][2 * p],     ah[mt], bh[0], bh[1]);
                    mma16816(acc[mt][2 * p + 1], ah[mt], bh[2], bh[3]);
                }
                // lh
#pragma unroll
                for (int mt = 0; mt < 4; ++mt) {
                    mma16816(acc[mt][2 * p],     al[mt], bh[0], bh[1]);
                    mma16816(acc[mt][2 * p + 1], al[mt], bh[2], bh[3]);
                }
            }
        }
        __syncthreads();
    }

    // ---------------- epilogue ----------------
    const int baseN = wn * 64 + 2 * (lane & 3);
#pragma unroll
    for (int mt = 0; mt < 4; ++mt) {
#pragma unroll
        for (int h = 0; h < 2; ++h) {
            int m = wm * 64 + mt * 16 + (lane >> 2) + h * 8;
            if (MODE == 0) {
                size_t gi = ((size_t)(b * 128 + y0) * 128 + m) * 256;
#pragma unroll
                for (int j = 0; j < 8; ++j) {
                    int n = baseN + j * 8;
                    float r0 = acc[mt][j][h * 2]     * dmod[b * 256 + n]     + bnoise[n];
                    float r1 = acc[mt][j][h * 2 + 1] * dmod[b * 256 + n + 1] + bnoise[n + 1];
                    r0 = (r0 >= 0.0f) ? r0 : 0.2f * r0;
                    r1 = (r1 >= 0.0f) ? r1 : 0.2f * r1;
                    u32 h0, l0, h1, l1;
                    hsplit(r0, h0, l0);
                    hsplit(r1, h1, l1);
                    *(u32*)(g_y1h + gi + n) = h0 | (h1 << 16);
                    *(u32*)(g_y1l + gi + n) = l0 | (l1 << 16);
                }
            } else {
#pragma unroll
                for (int j = 0; j < 8; ++j) {
                    int n = baseN + j * 8;
                    float r0 = acc[mt][j][h * 2]     * dmod[b * 256 + n]     + bnoise[n];
                    float r1 = acc[mt][j][h * 2 + 1] * dmod[b * 256 + n + 1] + bnoise[n + 1];
                    r0 = (r0 >= 0.0f) ? r0 : 0.2f * r0;
                    r1 = (r1 >= 0.0f) ? r1 : 0.2f * r1;
                    outp[((size_t)(b * 256 + n)     * 128 + y0) * 128 + m] = r0;
                    outp[((size_t)(b * 256 + n + 1) * 128 + y0) * 128 + m] = r1;
                }
            }
        }
    }
}

// ---------------- launch ----------------
extern "C" void kernel_launch(void* const* d_in, const int* in_sizes, int n_in,
                              void* d_out, int out_size) {
    (void)in_sizes; (void)n_in; (void)out_size;
    const float* x         = (const float*)d_in[0];
    const float* istyle    = (const float*)d_in[1];
    const float* w_style1  = (const float*)d_in[2];
    const float* b_style1  = (const float*)d_in[3];
    const float* w_style2  = (const float*)d_in[4];
    const float* b_style2  = (const float*)d_in[5];
    const float* b_noise1  = (const float*)d_in[7];
    const float* b_noise2  = (const float*)d_in[9];
    const float* conv1_w   = (const float*)d_in[10];
    const float* conv2_w   = (const float*)d_in[11];
    const float* conv1x1_w = (const float*)d_in[12];
    float* out = (float*)d_out;

    cudaFuncSetAttribute(k_convhmma<0>, cudaFuncAttributeMaxDynamicSharedMemorySize, SMEM_BYTES);
    cudaFuncSetAttribute(k_convhmma<1>, cudaFuncAttributeMaxDynamicSharedMemorySize, SMEM_BYTES);

    k_transpose<<<dim3(256, 16), 256>>>(x);
    k_upsplit<<<65536, 256>>>();
    k_styles<<<8, 256>>>(istyle, w_style1, b_style1, w_style2, b_style2);
    k_wsq<<<dim3(256, 2), 256>>>(conv1_w, conv2_w);
    k_demod<<<dim3(256, 4, 2), 256>>>();
    k_prepw1<<<dim3(36, 256), 256>>>(conv1_w);
    k_prepw2<<<dim3(40, 256), 256>>>(conv2_w, conv1x1_w);
    k_convhmma<0><<<dim3(128, 4), 256, SMEM_BYTES>>>(b_noise1, nullptr);
    k_convhmma<1><<<dim3(128, 4), 256, SMEM_BYTES>>>(b_noise2, out);
}

// round 9
// speedup vs baseline: 7.0655x; 1.5762x over previous
#include <cuda_runtime.h>
#include <cuda_fp16.h>
#include <cstdint>

typedef unsigned long long u64;
typedef unsigned int u32;

// ---------------- problem constants ----------------
constexpr int NB = 4, NC = 256, NO = 256;
constexpr int IH = 64, IW = 64, OH = 128, OW = 128;
constexpr size_t NELEM = (size_t)NB * NC * OH * OW;   // 16,777,216

// Stage buffer: A 16KB @0, B 32KB @16384 -> 48KB; double buffered.
constexpr u32 STAGE_BYTES = 49152;
constexpr u32 SMEM_BYTES = 2 * STAGE_BYTES;

// ---------------- device scratch ----------------
__device__ float g_xt[(size_t)NB * IH * IW * NC];            // NHWC fp32 (64x64)
__device__ __align__(128) __half g_xh[NELEM];                // NHWC fp16 upsampled x
__device__ __align__(128) __half g_y1h[NELEM];               // NHWC fp16 y1
__device__ __align__(128) __half g_B1h[4 * 9 * 256 * 256];   // [b*9+tap][oc][c]
__device__ __align__(128) __half g_B2h[4 * 10 * 256 * 256];  // [b*10+tap][oc][c]
__device__ float g_s1[NB * NC], g_s2[NB * NC];
__device__ float g_d1[NB * NO], g_d2[NB * NO];
__device__ float g_wsq1[NO * NC], g_wsq2[NO * NC];

// ---------------- helpers ----------------
__device__ __forceinline__ u32 smem_u32(const void* p) {
    u32 a;
    asm("{ .reg .u64 t; cvta.to.shared.u64 t, %1; cvt.u32.u64 %0, t; }" : "=r"(a) : "l"(p));
    return a;
}
__device__ __forceinline__ void ldsm4(u32* r, u32 addr) {
    asm volatile("ldmatrix.sync.aligned.m8n8.x4.shared.b16 {%0,%1,%2,%3}, [%4];"
                 : "=r"(r[0]), "=r"(r[1]), "=r"(r[2]), "=r"(r[3]) : "r"(addr));
}
__device__ __forceinline__ void mma16816(float* d, const u32* a, u32 b0, u32 b1) {
    asm volatile("mma.sync.aligned.m16n8k16.row.col.f32.f16.f16.f32 "
                 "{%0,%1,%2,%3}, {%4,%5,%6,%7}, {%8,%9}, {%0,%1,%2,%3};"
                 : "+f"(d[0]), "+f"(d[1]), "+f"(d[2]), "+f"(d[3])
                 : "r"(a[0]), "r"(a[1]), "r"(a[2]), "r"(a[3]), "r"(b0), "r"(b1));
}
__device__ __forceinline__ void cp16(u32 dst, const void* src, u32 sz) {
    asm volatile("cp.async.cg.shared.global [%0], [%1], 16, %2;"
                 :: "r"(dst), "l"(src), "r"(sz) : "memory");
}
__device__ __forceinline__ u32 swz(u32 off) { return off ^ ((off >> 3) & 0x70); }

// ---------------- 1) NCHW -> NHWC fp32 transpose (64x64) ----------------
__global__ void k_transpose(const float* __restrict__ x) {
    __shared__ float tile[32][33];
    int by = blockIdx.x;                 // b*64 + y
    int b = by >> 6, y = by & 63;
    int cblk = (blockIdx.y >> 1) * 32, xblk = (blockIdx.y & 1) * 32;
    int t = threadIdx.x;
    int ci = t >> 5, xi = t & 31;
#pragma unroll
    for (int p = 0; p < 4; ++p) {
        int c = cblk + p * 8 + ci;
        tile[p * 8 + ci][xi] = x[((size_t)(b * 256 + c) * 64 + y) * 64 + xblk + xi];
    }
    __syncthreads();
    int xi2 = t >> 5, c2 = t & 31;
#pragma unroll
    for (int p = 0; p < 4; ++p) {
        int xx = xblk + p * 8 + xi2;
        g_xt[((size_t)(b * 64 + y) * 64 + xx) * 256 + cblk + c2] = tile[c2][p * 8 + xi2];
    }
}

// ---------------- 2) bilinear 2x upsample -> fp16 (NHWC) ----------------
__global__ void k_uphalf() {
    int i = blockIdx.x * 256 + threadIdx.x;     // 16,777,216
    int c  = i & 255;
    int xo = (i >> 8) & 127;
    int yo = (i >> 15) & 127;
    int b  = i >> 22;

    int y0, x0; float fy, fx;
    if (yo & 1) { y0 = yo >> 1;       fy = 0.25f; }
    else        { y0 = (yo >> 1) - 1; fy = 0.75f; }
    if (xo & 1) { x0 = xo >> 1;       fx = 0.25f; }
    else        { x0 = (xo >> 1) - 1; fx = 0.75f; }
    int y1i = min(y0 + 1, IH - 1); y0 = max(y0, 0);
    int x1i = min(x0 + 1, IW - 1); x0 = max(x0, 0);

    const float* base = g_xt + (size_t)b * IH * IW * 256 + c;
    float v00 = base[(y0  * 64 + x0 ) * 256], v01 = base[(y0  * 64 + x1i) * 256];
    float v10 = base[(y1i * 64 + x0 ) * 256], v11 = base[(y1i * 64 + x1i) * 256];
    float vt = v00 + fx * (v01 - v00);
    float vb = v10 + fx * (v11 - v10);
    g_xh[i] = __float2half(vt + fy * (vb - vt));
}

// ---------------- 3) styles ----------------
__global__ void k_styles(const float* __restrict__ istyle,
                         const float* __restrict__ w1, const float* __restrict__ b1,
                         const float* __restrict__ w2, const float* __restrict__ b2) {
    int b = blockIdx.x & 3;
    int which = blockIdx.x >> 2;
    int c = threadIdx.x;
    const float* wrow = (which ? w2 : w1) + (size_t)c * 256;
    const float* ist = istyle + b * 256;
    float acc = (which ? b2 : b1)[c];
#pragma unroll 8
    for (int k = 0; k < 256; ++k) acc += ist[k] * wrow[k];
    (which ? g_s2 : g_s1)[b * 256 + c] = acc + 1.0f;
}

// ---------------- 4) wsq ----------------
__global__ void k_wsq(const float* __restrict__ w1, const float* __restrict__ w2) {
    int which = blockIdx.y;
    int i = blockIdx.x * 256 + threadIdx.x;
    const float* w = (which ? w2 : w1) + (size_t)i * 9;
    float s = 0.0f;
#pragma unroll
    for (int k = 0; k < 9; ++k) { float v = w[k]; s += v * v; }
    (which ? g_wsq2 : g_wsq1)[i] = s;
}

// ---------------- 5) demod ----------------
__global__ void k_demod() {
    int o = blockIdx.x, b = blockIdx.y, which = blockIdx.z;
    int c = threadIdx.x;
    const float* wsq = which ? g_wsq2 : g_wsq1;
    const float* s   = which ? g_s2  : g_s1;
    float sv = s[b * NC + c];
    float v = wsq[o * NC + c] * sv * sv;
    __shared__ float red[256];
    red[c] = v;
    __syncthreads();
    for (int st = 128; st; st >>= 1) {
        if (c < st) red[c] += red[c + st];
        __syncthreads();
    }
    if (c == 0) (which ? g_d2 : g_d1)[b * NO + o] = rsqrtf(red[0] + 1e-8f);
}

// ---------------- 6) weight prep: B[b,tap,oc,c] = W[oc,c,tap]*s[b,c] (fp16) ----------------
__global__ void k_prepw1(const float* __restrict__ w1) {
    int bt = blockIdx.x;            // b*9+tap
    int b = bt / 9, tap = bt % 9;
    int oc = blockIdx.y, c = threadIdx.x;
    float v = w1[((size_t)oc * 256 + c) * 9 + tap] * g_s1[b * 256 + c];
    g_B1h[((size_t)bt * 256 + oc) * 256 + c] = __float2half(v);
}
__global__ void k_prepw2(const float* __restrict__ w2, const float* __restrict__ w1x1) {
    int bt = blockIdx.x;            // b*10+tap
    int b = bt / 10, tap = bt % 10;
    int oc = blockIdx.y, c = threadIdx.x;
    float v;
    if (tap < 9) v = w2[((size_t)oc * 256 + c) * 9 + tap] * g_s2[b * 256 + c];
    else         v = w1x1[(size_t)oc * 256 + c] * (1.0f / g_d2[b * 256 + oc]);
    g_B2h[((size_t)bt * 256 + oc) * 256 + c] = __float2half(v);
}

// ---------------- 7) warp-MMA implicit-GEMM modulated conv (pure fp16) ----------------
// MODE 0: A = xh (9 taps), epilogue -> y1 fp16 NHWC.
// MODE 1: A = y1h (taps 0-8) + xh (tap 9 = folded 1x1 skip), epilogue -> out NCHW fp32.
// Per CTA: M=128 pixels (row y0) x N=256 oc. 8 warps (2M x 4N), warp tile m64 x n64.
template <int MODE>
__global__ void __launch_bounds__(256, 1) k_convhmma(const float* __restrict__ bnoise,
                                                     float* __restrict__ outp) {
    constexpr int NT = (MODE == 0) ? 9 : 10;
    constexpr int S = NT * 4;
    extern __shared__ __align__(1024) char smem[];
    const u32 sb = smem_u32(smem);
    const int t = threadIdx.x;
    const int y0 = blockIdx.x, b = blockIdx.y;
    const float* dmod = (MODE == 0) ? g_d1 : g_d2;

    const int warp = t >> 5, lane = t & 31;
    const int wm = warp & 1, wn = warp >> 1;      // 2 m-tiles x 4 n-tiles of 64
    const int li = lane >> 3, lr = lane & 7;

    // ldmatrix addressing: addr = tile + row*128 + ((colbyte + kadd) ^ ((row&7)*16))
    u32 aRow[4], aXor[4];
#pragma unroll
    for (int mt = 0; mt < 4; ++mt) {
        int row = wm * 64 + mt * 16 + lr + ((li & 1) << 3);
        aRow[mt] = (u32)row << 7;
        aXor[mt] = ((u32)row & 7u) << 4;
    }
    const u32 aCol = ((u32)li >> 1) << 4;
    u32 bRow[4], bXor[4];
#pragma unroll
    for (int p = 0; p < 4; ++p) {
        int row = wn * 64 + p * 16 + lr + ((li >> 1) << 3);
        bRow[p] = (u32)row << 7;
        bXor[p] = ((u32)row & 7u) << 4;
    }
    const u32 bCol = ((u32)li & 1u) << 4;

    float acc[4][8][4];
#pragma unroll
    for (int mt = 0; mt < 4; ++mt)
#pragma unroll
        for (int j = 0; j < 8; ++j)
#pragma unroll
            for (int q = 0; q < 4; ++q) acc[mt][j][q] = 0.0f;

    auto load_stage = [&](int s) {
        int tap = s >> 2, c0 = (s & 3) << 6;
        u32 base = sb + (u32)(s & 1) * STAGE_BYTES;
        const __half* A;
        int dy, dx;
        if (MODE == 1 && tap == 9) { A = g_xh; dy = 0; dx = 0; }
        else {
            dy = tap / 3 - 1; dx = tap % 3 - 1;
            A = (MODE == 0) ? g_xh : g_y1h;
        }
        int y = y0 + dy;
        bool yok = ((unsigned)y < 128u);
        int yc = min(max(y, 0), 127);
        // A tile: [128 m][64 c] fp16  (1024 vec16 / 256 thr = 4)
#pragma unroll
        for (int i = 0; i < 4; ++i) {
            int u = t + i * 256;
            int m = u >> 3, j = u & 7;
            int xx = m + dx;
            bool ok = yok && ((unsigned)xx < 128u);
            int xc = min(max(xx, 0), 127);
            const __half* src = A + ((size_t)((b * 128 + yc) * 128 + xc) * 256 + c0 + j * 8);
            u32 dst = base + swz(((u32)m << 7) + ((u32)j << 4));
            cp16(dst, src, ok ? 16u : 0u);
        }
        // B tile: [256 oc][64 c] fp16  (2048 vec16 / 256 thr = 8)
        const __half* Bh = (MODE == 0) ? g_B1h : g_B2h;
        size_t btbase = (size_t)(b * NT + tap) * 65536 + c0;
#pragma unroll
        for (int i = 0; i < 8; ++i) {
            int u = t + i * 256;
            int n = u >> 3, j = u & 7;
            const __half* src = Bh + (btbase + n * 256 + j * 8);
            u32 dst = base + 16384u + swz(((u32)n << 7) + ((u32)j << 4));
            cp16(dst, src, 16u);
        }
        asm volatile("cp.async.commit_group;" ::: "memory");
    };

    load_stage(0);
    for (int s = 0; s < S; ++s) {
        if (s + 1 < S) {
            load_stage(s + 1);
            asm volatile("cp.async.wait_group 1;" ::: "memory");
        } else {
            asm volatile("cp.async.wait_group 0;" ::: "memory");
        }
        __syncthreads();
        u32 base = sb + (u32)(s & 1) * STAGE_BYTES;
        const u32 boff = base + 16384u;
#pragma unroll
        for (int kk = 0; kk < 4; ++kk) {
            u32 kadd = (u32)kk << 5;
            u32 ak = aCol + kadd;
            u32 bk = bCol + kadd;
            u32 ah[4][4];
#pragma unroll
            for (int mt = 0; mt < 4; ++mt)
                ldsm4(ah[mt], base + aRow[mt] + (ak ^ aXor[mt]));
#pragma unroll
            for (int p = 0; p < 4; ++p) {
                u32 bh[4];
                ldsm4(bh, boff + bRow[p] + (bk ^ bXor[p]));
#pragma unroll
                for (int mt = 0; mt < 4; ++mt) {
                    mma16816(acc[mt][2 * p],     ah[mt], bh[0], bh[1]);
                    mma16816(acc[mt][2 * p + 1], ah[mt], bh[2], bh[3]);
                }
            }
        }
        __syncthreads();
    }

    // ---------------- epilogue ----------------
    const int baseN = wn * 64 + 2 * (lane & 3);
#pragma unroll
    for (int mt = 0; mt < 4; ++mt) {
#pragma unroll
        for (int h = 0; h < 2; ++h) {
            int m = wm * 64 + mt * 16 + (lane >> 2) + h * 8;
            if (MODE == 0) {
                size_t gi = ((size_t)(b * 128 + y0) * 128 + m) * 256;
#pragma unroll
                for (int j = 0; j < 8; ++j) {
                    int n = baseN + j * 8;
                    float r0 = acc[mt][j][h * 2]     * dmod[b * 256 + n]     + bnoise[n];
                    float r1 = acc[mt][j][h * 2 + 1] * dmod[b * 256 + n + 1] + bnoise[n + 1];
                    r0 = (r0 >= 0.0f) ? r0 : 0.2f * r0;
                    r1 = (r1 >= 0.0f) ? r1 : 0.2f * r1;
                    u32 h0 = (u32)__half_as_ushort(__float2half(r0));
                    u32 h1 = (u32)__half_as_ushort(__float2half(r1));
                    *(u32*)(g_y1h + gi + n) = h0 | (h1 << 16);
                }
            } else {
#pragma unroll
                for (int j = 0; j < 8; ++j) {
                    int n = baseN + j * 8;
                    float r0 = acc[mt][j][h * 2]     * dmod[b * 256 + n]     + bnoise[n];
                    float r1 = acc[mt][j][h * 2 + 1] * dmod[b * 256 + n + 1] + bnoise[n + 1];
                    r0 = (r0 >= 0.0f) ? r0 : 0.2f * r0;
                    r1 = (r1 >= 0.0f) ? r1 : 0.2f * r1;
                    outp[((size_t)(b * 256 + n)     * 128 + y0) * 128 + m] = r0;
                    outp[((size_t)(b * 256 + n + 1) * 128 + y0) * 128 + m] = r1;
                }
            }
        }
    }
}

// ---------------- launch ----------------
extern "C" void kernel_launch(void* const* d_in, const int* in_sizes, int n_in,
                              void* d_out, int out_size) {
    (void)in_sizes; (void)n_in; (void)out_size;
    const float* x         = (const float*)d_in[0];
    const float* istyle    = (const float*)d_in[1];
    const float* w_style1  = (const float*)d_in[2];
    const float* b_style1  = (const float*)d_in[3];
    const float* w_style2  = (const float*)d_in[4];
    const float* b_style2  = (const float*)d_in[5];
    const float* b_noise1  = (const float*)d_in[7];
    const float* b_noise2  = (const float*)d_in[9];
    const float* conv1_w   = (const float*)d_in[10];
    const float* conv2_w   = (const float*)d_in[11];
    const float* conv1x1_w = (const float*)d_in[12];
    float* out = (float*)d_out;

    cudaFuncSetAttribute(k_convhmma<0>, cudaFuncAttributeMaxDynamicSharedMemorySize, SMEM_BYTES);
    cudaFuncSetAttribute(k_convhmma<1>, cudaFuncAttributeMaxDynamicSharedMemorySize, SMEM_BYTES);

    k_transpose<<<dim3(256, 16), 256>>>(x);
    k_uphalf<<<65536, 256>>>();
    k_styles<<<8, 256>>>(istyle, w_style1, b_style1, w_style2, b_style2);
    k_wsq<<<dim3(256, 2), 256>>>(conv1_w, conv2_w);
    k_demod<<<dim3(256, 4, 2), 256>>>();
    k_prepw1<<<dim3(36, 256), 256>>>(conv1_w);
    k_prepw2<<<dim3(40, 256), 256>>>(conv2_w, conv1x1_w);
    k_convhmma<0><<<dim3(128, 4), 256, SMEM_BYTES>>>(b_noise1, nullptr);
    k_convhmma<1><<<dim3(128, 4), 256, SMEM_BYTES>>>(b_noise2, out);
}

// round 10
// speedup vs baseline: 7.9432x; 1.1242x over previous
#include <cuda_runtime.h>
#include <cuda_fp16.h>
#include <cstdint>

typedef unsigned long long u64;
typedef unsigned int u32;

// ---------------- problem constants ----------------
constexpr int NB = 4, NC = 256, NO = 256;
constexpr int IH = 64, IW = 64, OH = 128, OW = 128;
constexpr size_t NELEM = (size_t)NB * NC * OH * OW;   // 16,777,216

// Stage buffer: A tile [128 m][128 c] fp16 = 32KB; double buffered.
constexpr u32 STAGE_BYTES = 32768;
constexpr u32 SMEM_BYTES = 2 * STAGE_BYTES;

// ---------------- device scratch ----------------
__device__ float g_xt[(size_t)NB * IH * IW * NC];            // NHWC fp32 (64x64)
__device__ __align__(128) __half g_xh[NELEM];                // NHWC fp16 upsampled x
__device__ __align__(128) __half g_y1h[NELEM];               // NHWC fp16 y1
// B in mma fragment layout: [bt][ck(16)][ntile(16)][lane(32)] -> uint4
__device__ __align__(16) u32 g_Bf1[36 * 16 * 16 * 32 * 4 / 1];   // 1,179,648 u32 worth: see below
__device__ __align__(16) u32 g_Bf2[40 * 16 * 16 * 128];          // 1,310,720 u32
// (g_Bf1 correct size: 36*16*16*128 = 1,179,648)
__device__ float g_s1[NB * NC], g_s2[NB * NC];
__device__ float g_d1[NB * NO], g_d2[NB * NO];
__device__ float g_wsq1[NO * NC], g_wsq2[NO * NC];

// ---------------- helpers ----------------
__device__ __forceinline__ u32 smem_u32(const void* p) {
    u32 a;
    asm("{ .reg .u64 t; cvta.to.shared.u64 t, %1; cvt.u32.u64 %0, t; }" : "=r"(a) : "l"(p));
    return a;
}
__device__ __forceinline__ void ldsm4(u32* r, u32 addr) {
    asm volatile("ldmatrix.sync.aligned.m8n8.x4.shared.b16 {%0,%1,%2,%3}, [%4];"
                 : "=r"(r[0]), "=r"(r[1]), "=r"(r[2]), "=r"(r[3]) : "r"(addr));
}
__device__ __forceinline__ void mma16816(float* d, const u32* a, u32 b0, u32 b1) {
    asm volatile("mma.sync.aligned.m16n8k16.row.col.f32.f16.f16.f32 "
                 "{%0,%1,%2,%3}, {%4,%5,%6,%7}, {%8,%9}, {%0,%1,%2,%3};"
                 : "+f"(d[0]), "+f"(d[1]), "+f"(d[2]), "+f"(d[3])
                 : "r"(a[0]), "r"(a[1]), "r"(a[2]), "r"(a[3]), "r"(b0), "r"(b1));
}
__device__ __forceinline__ void cp16(u32 dst, const void* src, u32 sz) {
    asm volatile("cp.async.cg.shared.global [%0], [%1], 16, %2;"
                 :: "r"(dst), "l"(src), "r"(sz) : "memory");
}

// ---------------- 1) NCHW -> NHWC fp32 transpose (64x64) ----------------
__global__ void k_transpose(const float* __restrict__ x) {
    __shared__ float tile[32][33];
    int by = blockIdx.x;                 // b*64 + y
    int b = by >> 6, y = by & 63;
    int cblk = (blockIdx.y >> 1) * 32, xblk = (blockIdx.y & 1) * 32;
    int t = threadIdx.x;
    int ci = t >> 5, xi = t & 31;
#pragma unroll
    for (int p = 0; p < 4; ++p) {
        int c = cblk + p * 8 + ci;
        tile[p * 8 + ci][xi] = x[((size_t)(b * 256 + c) * 64 + y) * 64 + xblk + xi];
    }
    __syncthreads();
    int xi2 = t >> 5, c2 = t & 31;
#pragma unroll
    for (int p = 0; p < 4; ++p) {
        int xx = xblk + p * 8 + xi2;
        g_xt[((size_t)(b * 64 + y) * 64 + xx) * 256 + cblk + c2] = tile[c2][p * 8 + xi2];
    }
}

// ---------------- 2) bilinear 2x upsample -> fp16 (NHWC) ----------------
__global__ void k_uphalf() {
    int i = blockIdx.x * 256 + threadIdx.x;     // 16,777,216
    int c  = i & 255;
    int xo = (i >> 8) & 127;
    int yo = (i >> 15) & 127;
    int b  = i >> 22;

    int y0, x0; float fy, fx;
    if (yo & 1) { y0 = yo >> 1;       fy = 0.25f; }
    else        { y0 = (yo >> 1) - 1; fy = 0.75f; }
    if (xo & 1) { x0 = xo >> 1;       fx = 0.25f; }
    else        { x0 = (xo >> 1) - 1; fx = 0.75f; }
    int y1i = min(y0 + 1, IH - 1); y0 = max(y0, 0);
    int x1i = min(x0 + 1, IW - 1); x0 = max(x0, 0);

    const float* base = g_xt + (size_t)b * IH * IW * 256 + c;
    float v00 = base[(y0  * 64 + x0 ) * 256], v01 = base[(y0  * 64 + x1i) * 256];
    float v10 = base[(y1i * 64 + x0 ) * 256], v11 = base[(y1i * 64 + x1i) * 256];
    float vt = v00 + fx * (v01 - v00);
    float vb = v10 + fx * (v11 - v10);
    g_xh[i] = __float2half(vt + fy * (vb - vt));
}

// ---------------- 3) styles ----------------
__global__ void k_styles(const float* __restrict__ istyle,
                         const float* __restrict__ w1, const float* __restrict__ b1,
                         const float* __restrict__ w2, const float* __restrict__ b2) {
    int b = blockIdx.x & 3;
    int which = blockIdx.x >> 2;
    int c = threadIdx.x;
    const float* wrow = (which ? w2 : w1) + (size_t)c * 256;
    const float* ist = istyle + b * 256;
    float acc = (which ? b2 : b1)[c];
#pragma unroll 8
    for (int k = 0; k < 256; ++k) acc += ist[k] * wrow[k];
    (which ? g_s2 : g_s1)[b * 256 + c] = acc + 1.0f;
}

// ---------------- 4) wsq ----------------
__global__ void k_wsq(const float* __restrict__ w1, const float* __restrict__ w2) {
    int which = blockIdx.y;
    int i = blockIdx.x * 256 + threadIdx.x;
    const float* w = (which ? w2 : w1) + (size_t)i * 9;
    float s = 0.0f;
#pragma unroll
    for (int k = 0; k < 9; ++k) { float v = w[k]; s += v * v; }
    (which ? g_wsq2 : g_wsq1)[i] = s;
}

// ---------------- 5) demod ----------------
__global__ void k_demod() {
    int o = blockIdx.x, b = blockIdx.y, which = blockIdx.z;
    int c = threadIdx.x;
    const float* wsq = which ? g_wsq2 : g_wsq1;
    const float* s   = which ? g_s2  : g_s1;
    float sv = s[b * NC + c];
    float v = wsq[o * NC + c] * sv * sv;
    __shared__ float red[256];
    red[c] = v;
    __syncthreads();
    for (int st = 128; st; st >>= 1) {
        if (c < st) red[c] += red[c + st];
        __syncthreads();
    }
    if (c == 0) (which ? g_d2 : g_d1)[b * NO + o] = rsqrtf(red[0] + 1e-8f);
}

// ---------------- 6) weight prep directly in mma B-fragment layout ----------------
// Fragment definition (derived from the verified R9 ldsm pattern):
// for (bt, ck, ntile, lane): with n0 = ntile*16 + (lane>>2), c0 = ck*16 + 2*(lane&3):
//   u32[0] = half2( v(n0,   c0),   v(n0,   c0+1) )
//   u32[1] = half2( v(n0,   c0+8), v(n0,   c0+9) )
//   u32[2] = half2( v(n0+8, c0),   v(n0+8, c0+1) )
//   u32[3] = half2( v(n0+8, c0+8), v(n0+8, c0+9) )
template <int MODE>
__global__ void k_prepfrag(const float* __restrict__ w, const float* __restrict__ w1x1) {
    constexpr int NT = (MODE == 0) ? 9 : 10;
    int bt = blockIdx.x;                   // b*NT + tap
    int ck = blockIdx.y;                   // 0..15
    int b = bt / NT, tap = bt % NT;
    int job = threadIdx.x;                 // 512: ntile*32 + lane
    int ntile = job >> 5, lane = job & 31;
    int n0 = ntile * 16 + (lane >> 2);
    int c0 = ck * 16 + 2 * (lane & 3);
    const float* s = (MODE == 0) ? g_s1 : g_s2;

    u32 o[4];
#pragma unroll
    for (int qn = 0; qn < 2; ++qn) {
#pragma unroll
        for (int qk = 0; qk < 2; ++qk) {
            int oc = n0 + qn * 8, c = c0 + qk * 8;
            float v0, v1;
            if (MODE == 1 && tap == 9) {
                float inv = 1.0f / g_d2[b * 256 + oc];
                v0 = w1x1[(size_t)oc * 256 + c] * inv;
                v1 = w1x1[(size_t)oc * 256 + c + 1] * inv;
            } else {
                v0 = w[((size_t)oc * 256 + c) * 9 + tap] * s[b * 256 + c];
                v1 = w[((size_t)oc * 256 + c + 1) * 9 + tap] * s[b * 256 + c + 1];
            }
            o[qn * 2 + qk] = (u32)__half_as_ushort(__float2half(v0))
                           | ((u32)__half_as_ushort(__float2half(v1)) << 16);
        }
    }
    size_t idx = (((size_t)bt * 16 + ck) * 16 + ntile) * 32 + lane;
    ((uint4*)(MODE == 0 ? g_Bf1 : g_Bf2))[idx] = make_uint4(o[0], o[1], o[2], o[3]);
}

// ---------------- 7) warp-MMA implicit-GEMM conv: A via smem/ldsm, B via LDG fragments ----
// MODE 0: A = xh (9 taps), epilogue -> y1 fp16 NHWC.
// MODE 1: A = y1h (taps 0-8) + xh (tap 9 = folded 1x1 skip), epilogue -> out NCHW fp32.
// Per CTA: M=128 pixels (row y0) x N=256 oc. 8 warps (2M x 4N), warp tile m64 x n64.
// Stage = (tap, 128-channel chunk): S = NT*2 stages, kk = 8 k16 steps per stage.
template <int MODE>
__global__ void __launch_bounds__(256, 1) k_convhmma(const float* __restrict__ bnoise,
                                                     float* __restrict__ outp) {
    constexpr int NT = (MODE == 0) ? 9 : 10;
    constexpr int S = NT * 2;
    extern __shared__ __align__(1024) char smem[];
    const u32 sb = smem_u32(smem);
    const int t = threadIdx.x;
    const int y0 = blockIdx.x, b = blockIdx.y;
    const float* dmod = (MODE == 0) ? g_d1 : g_d2;
    const uint4* __restrict__ Bf = (const uint4*)((MODE == 0) ? g_Bf1 : g_Bf2);

    const int warp = t >> 5, lane = t & 31;
    const int wm = warp & 1, wn = warp >> 1;      // 2 m-tiles x 4 n-tiles of 64
    const int li = lane >> 3, lr = lane & 7;

    // A ldsm addressing: addr = tile + row*256 + ((colbyte) ^ ((row&7)*16))
    u32 aRow[4], aXor[4];
#pragma unroll
    for (int mt = 0; mt < 4; ++mt) {
        int row = wm * 64 + mt * 16 + lr + ((li & 1) << 3);
        aRow[mt] = (u32)row << 8;
        aXor[mt] = ((u32)row & 7u) << 4;
    }
    const u32 aCol = ((u32)li >> 1) << 4;

    float acc[4][8][4];
#pragma unroll
    for (int mt = 0; mt < 4; ++mt)
#pragma unroll
        for (int j = 0; j < 8; ++j)
#pragma unroll
            for (int q = 0; q < 4; ++q) acc[mt][j][q] = 0.0f;

    auto load_stageA = [&](int s) {
        int tap = s >> 1, c0 = (s & 1) << 7;
        u32 base = sb + (u32)(s & 1) * STAGE_BYTES;
        const __half* A;
        int dy, dx;
        if (MODE == 1 && tap == 9) { A = g_xh; dy = 0; dx = 0; }
        else {
            dy = tap / 3 - 1; dx = tap % 3 - 1;
            A = (MODE == 0) ? g_xh : g_y1h;
        }
        int y = y0 + dy;
        bool yok = ((unsigned)y < 128u);
        int yc = min(max(y, 0), 127);
        // A tile: [128 m][128 c] fp16  (2048 vec16 / 256 thr = 8)
#pragma unroll
        for (int i = 0; i < 8; ++i) {
            int u = t + i * 256;
            int m = u >> 4, j = u & 15;
            int xx = m + dx;
            bool ok = yok && ((unsigned)xx < 128u);
            int xc = min(max(xx, 0), 127);
            const __half* src = A + ((size_t)((b * 128 + yc) * 128 + xc) * 256 + c0 + j * 8);
            u32 dst = base + ((u32)m << 8) + ((((u32)j << 4)) ^ (((u32)m & 7u) << 4));
            cp16(dst, src, ok ? 16u : 0u);
        }
        asm volatile("cp.async.commit_group;" ::: "memory");
    };

    load_stageA(0);
    for (int s = 0; s < S; ++s) {
        const int tap = s >> 1;
        const int ckb = (s & 1) * 8;
        // B fragment base index (uint4 units): [bt][ck][ntile][lane]; kk step = 16*32 = 512.
        const size_t bbase = (((size_t)(b * NT + tap) * 16 + ckb) * 16 + wn * 4) * 32 + lane;

        uint4 bq[2][4];
#pragma unroll
        for (int p = 0; p < 4; ++p) bq[0][p] = __ldg(Bf + bbase + p * 32);

        if (s + 1 < S) {
            load_stageA(s + 1);
            asm volatile("cp.async.wait_group 1;" ::: "memory");
        } else {
            asm volatile("cp.async.wait_group 0;" ::: "memory");
        }
        __syncthreads();

        const u32 abase = sb + (u32)(s & 1) * STAGE_BYTES;
#pragma unroll
        for (int kk = 0; kk < 8; ++kk) {
            if (kk < 7) {
#pragma unroll
                for (int p = 0; p < 4; ++p)
                    bq[(kk + 1) & 1][p] = __ldg(Bf + bbase + (size_t)(kk + 1) * 512 + p * 32);
            }
            u32 ak = aCol + ((u32)kk << 5);
            u32 ah[4][4];
#pragma unroll
            for (int mt = 0; mt < 4; ++mt)
                ldsm4(ah[mt], abase + aRow[mt] + (ak ^ aXor[mt]));
#pragma unroll
            for (int p = 0; p < 4; ++p) {
                uint4 q = bq[kk & 1][p];
#pragma unroll
                for (int mt = 0; mt < 4; ++mt) {
                    mma16816(acc[mt][2 * p],     ah[mt], q.x, q.y);
                    mma16816(acc[mt][2 * p + 1], ah[mt], q.z, q.w);
                }
            }
        }
        __syncthreads();
    }

    // ---------------- epilogue ----------------
    const int baseN = wn * 64 + 2 * (lane & 3);
#pragma unroll
    for (int mt = 0; mt < 4; ++mt) {
#pragma unroll
        for (int h = 0; h < 2; ++h) {
            int m = wm * 64 + mt * 16 + (lane >> 2) + h * 8;
            if (MODE == 0) {
                size_t gi = ((size_t)(b * 128 + y0) * 128 + m) * 256;
#pragma unroll
                for (int j = 0; j < 8; ++j) {
                    int n = baseN + j * 8;
                    float r0 = acc[mt][j][h * 2]     * dmod[b * 256 + n]     + bnoise[n];
                    float r1 = acc[mt][j][h * 2 + 1] * dmod[b * 256 + n + 1] + bnoise[n + 1];
                    r0 = (r0 >= 0.0f) ? r0 : 0.2f * r0;
                    r1 = (r1 >= 0.0f) ? r1 : 0.2f * r1;
                    u32 h0 = (u32)__half_as_ushort(__float2half(r0));
                    u32 h1 = (u32)__half_as_ushort(__float2half(r1));
                    *(u32*)(g_y1h + gi + n) = h0 | (h1 << 16);
                }
            } else {
#pragma unroll
                for (int j = 0; j < 8; ++j) {
                    int n = baseN + j * 8;
                    float r0 = acc[mt][j][h * 2]     * dmod[b * 256 + n]     + bnoise[n];
                    float r1 = acc[mt][j][h * 2 + 1] * dmod[b * 256 + n + 1] + bnoise[n + 1];
                    r0 = (r0 >= 0.0f) ? r0 : 0.2f * r0;
                    r1 = (r1 >= 0.0f) ? r1 : 0.2f * r1;
                    outp[((size_t)(b * 256 + n)     * 128 + y0) * 128 + m] = r0;
                    outp[((size_t)(b * 256 + n + 1) * 128 + y0) * 128 + m] = r1;
                }
            }
        }
    }
}

// ---------------- launch ----------------
extern "C" void kernel_launch(void* const* d_in, const int* in_sizes, int n_in,
                              void* d_out, int out_size) {
    (void)in_sizes; (void)n_in; (void)out_size;
    const float* x         = (const float*)d_in[0];
    const float* istyle    = (const float*)d_in[1];
    const float* w_style1  = (const float*)d_in[2];
    const float* b_style1  = (const float*)d_in[3];
    const float* w_style2  = (const float*)d_in[4];
    const float* b_style2  = (const float*)d_in[5];
    const float* b_noise1  = (const float*)d_in[7];
    const float* b_noise2  = (const float*)d_in[9];
    const float* conv1_w   = (const float*)d_in[10];
    const float* conv2_w   = (const float*)d_in[11];
    const float* conv1x1_w = (const float*)d_in[12];
    float* out = (float*)d_out;

    cudaFuncSetAttribute(k_convhmma<0>, cudaFuncAttributeMaxDynamicSharedMemorySize, SMEM_BYTES);
    cudaFuncSetAttribute(k_convhmma<1>, cudaFuncAttributeMaxDynamicSharedMemorySize, SMEM_BYTES);

    k_transpose<<<dim3(256, 16), 256>>>(x);
    k_uphalf<<<65536, 256>>>();
    k_styles<<<8, 256>>>(istyle, w_style1, b_style1, w_style2, b_style2);
    k_wsq<<<dim3(256, 2), 256>>>(conv1_w, conv2_w);
    k_demod<<<dim3(256, 4, 2), 256>>>();
    k_prepfrag<0><<<dim3(36, 16), 512>>>(conv1_w, nullptr);
    k_prepfrag<1><<<dim3(40, 16), 512>>>(conv2_w, conv1x1_w);
    k_convhmma<0><<<dim3(128, 4), 256, SMEM_BYTES>>>(b_noise1, nullptr);
    k_convhmma<1><<<dim3(128, 4), 256, SMEM_BYTES>>>(b_noise2, out);
}

// round 11
// speedup vs baseline: 8.9759x; 1.1300x over previous
#include <cuda_runtime.h>
#include <cuda_fp16.h>
#include <cstdint>

typedef unsigned long long u64;
typedef unsigned int u32;

// ---------------- problem constants ----------------
constexpr int NB = 4, NC = 256, NO = 256;
constexpr int IH = 64, IW = 64, OH = 128, OW = 128;
constexpr size_t NELEM = (size_t)NB * NC * OH * OW;   // 16,777,216

// Stage buffer: A tile [128 m][128 c] fp16 = 32KB; double buffered.
constexpr u32 STAGE_BYTES = 32768;
constexpr u32 SMEM_BYTES = 2 * STAGE_BYTES;

// ---------------- device scratch ----------------
__device__ float g_xt[(size_t)NB * IH * IW * NC];            // NHWC fp32 (64x64)
__device__ __align__(128) __half g_xh[NELEM];                // NHWC fp16 upsampled x
__device__ __align__(128) __half g_y1h[NELEM];               // NHWC fp16 y1
// B in mma fragment layout: [bt][ck(16)][ntile(16)][lane(32)] -> uint4
__device__ __align__(16) u32 g_Bf1[36 * 16 * 16 * 128];      // 1,179,648 u32
__device__ __align__(16) u32 g_Bf2[40 * 16 * 16 * 128];      // 1,310,720 u32
__device__ float g_s1[NB * NC], g_s2[NB * NC];
__device__ float g_d1[NB * NO], g_d2[NB * NO];
__device__ float g_wsq1[NO * NC], g_wsq2[NO * NC];

// ---------------- helpers ----------------
__device__ __forceinline__ u32 smem_u32(const void* p) {
    u32 a;
    asm("{ .reg .u64 t; cvta.to.shared.u64 t, %1; cvt.u32.u64 %0, t; }" : "=r"(a) : "l"(p));
    return a;
}
__device__ __forceinline__ void ldsm4(u32* r, u32 addr) {
    asm volatile("ldmatrix.sync.aligned.m8n8.x4.shared.b16 {%0,%1,%2,%3}, [%4];"
                 : "=r"(r[0]), "=r"(r[1]), "=r"(r[2]), "=r"(r[3]) : "r"(addr));
}
__device__ __forceinline__ void mma16816(float* d, const u32* a, u32 b0, u32 b1) {
    asm volatile("mma.sync.aligned.m16n8k16.row.col.f32.f16.f16.f32 "
                 "{%0,%1,%2,%3}, {%4,%5,%6,%7}, {%8,%9}, {%0,%1,%2,%3};"
                 : "+f"(d[0]), "+f"(d[1]), "+f"(d[2]), "+f"(d[3])
                 : "r"(a[0]), "r"(a[1]), "r"(a[2]), "r"(a[3]), "r"(b0), "r"(b1));
}
__device__ __forceinline__ void cp16(u32 dst, const void* src, u32 sz) {
    asm volatile("cp.async.cg.shared.global [%0], [%1], 16, %2;"
                 :: "r"(dst), "l"(src), "r"(sz) : "memory");
}

// ---------------- 1) NCHW -> NHWC fp32 transpose (64x64) ----------------
__global__ void k_transpose(const float* __restrict__ x) {
    __shared__ float tile[32][33];
    int by = blockIdx.x;                 // b*64 + y
    int b = by >> 6, y = by & 63;
    int cblk = (blockIdx.y >> 1) * 32, xblk = (blockIdx.y & 1) * 32;
    int t = threadIdx.x;
    int ci = t >> 5, xi = t & 31;
#pragma unroll
    for (int p = 0; p < 4; ++p) {
        int c = cblk + p * 8 + ci;
        tile[p * 8 + ci][xi] = x[((size_t)(b * 256 + c) * 64 + y) * 64 + xblk + xi];
    }
    __syncthreads();
    int xi2 = t >> 5, c2 = t & 31;
#pragma unroll
    for (int p = 0; p < 4; ++p) {
        int xx = xblk + p * 8 + xi2;
        g_xt[((size_t)(b * 64 + y) * 64 + xx) * 256 + cblk + c2] = tile[c2][p * 8 + xi2];
    }
}

// ---------------- 2) bilinear 2x upsample -> fp16 (NHWC) ----------------
__global__ void k_uphalf() {
    int i = blockIdx.x * 256 + threadIdx.x;     // 16,777,216
    int c  = i & 255;
    int xo = (i >> 8) & 127;
    int yo = (i >> 15) & 127;
    int b  = i >> 22;

    int y0, x0; float fy, fx;
    if (yo & 1) { y0 = yo >> 1;       fy = 0.25f; }
    else        { y0 = (yo >> 1) - 1; fy = 0.75f; }
    if (xo & 1) { x0 = xo >> 1;       fx = 0.25f; }
    else        { x0 = (xo >> 1) - 1; fx = 0.75f; }
    int y1i = min(y0 + 1, IH - 1); y0 = max(y0, 0);
    int x1i = min(x0 + 1, IW - 1); x0 = max(x0, 0);

    const float* base = g_xt + (size_t)b * IH * IW * 256 + c;
    float v00 = base[(y0  * 64 + x0 ) * 256], v01 = base[(y0  * 64 + x1i) * 256];
    float v10 = base[(y1i * 64 + x0 ) * 256], v11 = base[(y1i * 64 + x1i) * 256];
    float vt = v00 + fx * (v01 - v00);
    float vb = v10 + fx * (v11 - v10);
    g_xh[i] = __float2half(vt + fy * (vb - vt));
}

// ---------------- 3) styles ----------------
__global__ void k_styles(const float* __restrict__ istyle,
                         const float* __restrict__ w1, const float* __restrict__ b1,
                         const float* __restrict__ w2, const float* __restrict__ b2) {
    int b = blockIdx.x & 3;
    int which = blockIdx.x >> 2;
    int c = threadIdx.x;
    const float* wrow = (which ? w2 : w1) + (size_t)c * 256;
    const float* ist = istyle + b * 256;
    float acc = (which ? b2 : b1)[c];
#pragma unroll 8
    for (int k = 0; k < 256; ++k) acc += ist[k] * wrow[k];
    (which ? g_s2 : g_s1)[b * 256 + c] = acc + 1.0f;
}

// ---------------- 4) wsq ----------------
__global__ void k_wsq(const float* __restrict__ w1, const float* __restrict__ w2) {
    int which = blockIdx.y;
    int i = blockIdx.x * 256 + threadIdx.x;
    const float* w = (which ? w2 : w1) + (size_t)i * 9;
    float s = 0.0f;
#pragma unroll
    for (int k = 0; k < 9; ++k) { float v = w[k]; s += v * v; }
    (which ? g_wsq2 : g_wsq1)[i] = s;
}

// ---------------- 5) demod ----------------
__global__ void k_demod() {
    int o = blockIdx.x, b = blockIdx.y, which = blockIdx.z;
    int c = threadIdx.x;
    const float* wsq = which ? g_wsq2 : g_wsq1;
    const float* s   = which ? g_s2  : g_s1;
    float sv = s[b * NC + c];
    float v = wsq[o * NC + c] * sv * sv;
    __shared__ float red[256];
    red[c] = v;
    __syncthreads();
    for (int st = 128; st; st >>= 1) {
        if (c < st) red[c] += red[c + st];
        __syncthreads();
    }
    if (c == 0) (which ? g_d2 : g_d1)[b * NO + o] = rsqrtf(red[0] + 1e-8f);
}

// ---------------- 6) weight prep directly in mma B-fragment layout ----------------
// for (bt, ck, ntile, lane): with n0 = ntile*16 + (lane>>2), c0 = ck*16 + 2*(lane&3):
//   u32[0] = half2( v(n0,   c0),   v(n0,   c0+1) )
//   u32[1] = half2( v(n0,   c0+8), v(n0,   c0+9) )
//   u32[2] = half2( v(n0+8, c0),   v(n0+8, c0+1) )
//   u32[3] = half2( v(n0+8, c0+8), v(n0+8, c0+9) )
template <int MODE>
__global__ void k_prepfrag(const float* __restrict__ w, const float* __restrict__ w1x1) {
    constexpr int NT = (MODE == 0) ? 9 : 10;
    int bt = blockIdx.x;                   // b*NT + tap
    int ck = blockIdx.y;                   // 0..15
    int b = bt / NT, tap = bt % NT;
    int job = threadIdx.x;                 // 512: ntile*32 + lane
    int ntile = job >> 5, lane = job & 31;
    int n0 = ntile * 16 + (lane >> 2);
    int c0 = ck * 16 + 2 * (lane & 3);
    const float* s = (MODE == 0) ? g_s1 : g_s2;

    u32 o[4];
#pragma unroll
    for (int qn = 0; qn < 2; ++qn) {
#pragma unroll
        for (int qk = 0; qk < 2; ++qk) {
            int oc = n0 + qn * 8, c = c0 + qk * 8;
            float v0, v1;
            if (MODE == 1 && tap == 9) {
                float inv = 1.0f / g_d2[b * 256 + oc];
                v0 = w1x1[(size_t)oc * 256 + c] * inv;
                v1 = w1x1[(size_t)oc * 256 + c + 1] * inv;
            } else {
                v0 = w[((size_t)oc * 256 + c) * 9 + tap] * s[b * 256 + c];
                v1 = w[((size_t)oc * 256 + c + 1) * 9 + tap] * s[b * 256 + c + 1];
            }
            o[qn * 2 + qk] = (u32)__half_as_ushort(__float2half(v0))
                           | ((u32)__half_as_ushort(__float2half(v1)) << 16);
        }
    }
    size_t idx = (((size_t)bt * 16 + ck) * 16 + ntile) * 32 + lane;
    ((uint4*)(MODE == 0 ? g_Bf1 : g_Bf2))[idx] = make_uint4(o[0], o[1], o[2], o[3]);
}

// ---------------- 7) warp-MMA implicit-GEMM conv: 2 CTAs/SM via N-split ----------------
// MODE 0: A = xh (9 taps), epilogue -> y1 fp16 NHWC.
// MODE 1: A = y1h (taps 0-8) + xh (tap 9 = folded 1x1 skip), epilogue -> out NCHW fp32.
// Per CTA: M=128 pixels (row y0) x N=128 oc (half, by blockIdx.y).
// 8 warps (2M x 4N), warp tile m64 x n32 -> acc 64 regs; __launch_bounds__(256,2).
template <int MODE>
__global__ void __launch_bounds__(256, 2) k_convhmma(const float* __restrict__ bnoise,
                                                     float* __restrict__ outp) {
    constexpr int NT = (MODE == 0) ? 9 : 10;
    constexpr int S = NT * 2;
    extern __shared__ __align__(1024) char smem[];
    const u32 sb = smem_u32(smem);
    const int t = threadIdx.x;
    const int y0 = blockIdx.x, nh = blockIdx.y, b = blockIdx.z;
    const float* dmod = (MODE == 0) ? g_d1 : g_d2;
    const uint4* __restrict__ Bf = (const uint4*)((MODE == 0) ? g_Bf1 : g_Bf2);

    const int warp = t >> 5, lane = t & 31;
    const int wm = warp & 1, wn = warp >> 1;      // 2 m-tiles(64) x 4 n-tiles(32)
    const int li = lane >> 3, lr = lane & 7;

    // A ldsm addressing: addr = tile + row*256 + (colbyte ^ ((row&7)*16))
    u32 aRow[4], aXor[4];
#pragma unroll
    for (int mt = 0; mt < 4; ++mt) {
        int row = wm * 64 + mt * 16 + lr + ((li & 1) << 3);
        aRow[mt] = (u32)row << 8;
        aXor[mt] = ((u32)row & 7u) << 4;
    }
    const u32 aCol = ((u32)li >> 1) << 4;

    float acc[4][4][4];
#pragma unroll
    for (int mt = 0; mt < 4; ++mt)
#pragma unroll
        for (int j = 0; j < 4; ++j)
#pragma unroll
            for (int q = 0; q < 4; ++q) acc[mt][j][q] = 0.0f;

    auto load_stageA = [&](int s) {
        int tap = s >> 1, c0 = (s & 1) << 7;
        u32 base = sb + (u32)(s & 1) * STAGE_BYTES;
        const __half* A;
        int dy, dx;
        if (MODE == 1 && tap == 9) { A = g_xh; dy = 0; dx = 0; }
        else {
            dy = tap / 3 - 1; dx = tap % 3 - 1;
            A = (MODE == 0) ? g_xh : g_y1h;
        }
        int y = y0 + dy;
        bool yok = ((unsigned)y < 128u);
        int yc = min(max(y, 0), 127);
        // A tile: [128 m][128 c] fp16  (2048 vec16 / 256 thr = 8)
#pragma unroll
        for (int i = 0; i < 8; ++i) {
            int u = t + i * 256;
            int m = u >> 4, j = u & 15;
            int xx = m + dx;
            bool ok = yok && ((unsigned)xx < 128u);
            int xc = min(max(xx, 0), 127);
            const __half* src = A + ((size_t)((b * 128 + yc) * 128 + xc) * 256 + c0 + j * 8);
            u32 dst = base + ((u32)m << 8) + ((((u32)j << 4)) ^ (((u32)m & 7u) << 4));
            cp16(dst, src, ok ? 16u : 0u);
        }
        asm volatile("cp.async.commit_group;" ::: "memory");
    };

    load_stageA(0);
    for (int s = 0; s < S; ++s) {
        const int tap = s >> 1;
        const int ckb = (s & 1) * 8;
        // B frag idx (uint4): [bt][ck][ntile][lane]; this CTA's ntiles = nh*8 + wn*2 + p.
        const size_t bbase = (((size_t)(b * NT + tap) * 16 + ckb) * 16 + nh * 8 + wn * 2) * 32 + lane;

        uint4 bq[2][2];
#pragma unroll
        for (int p = 0; p < 2; ++p) bq[0][p] = __ldg(Bf + bbase + p * 32);

        if (s + 1 < S) {
            load_stageA(s + 1);
            asm volatile("cp.async.wait_group 1;" ::: "memory");
        } else {
            asm volatile("cp.async.wait_group 0;" ::: "memory");
        }
        __syncthreads();

        const u32 abase = sb + (u32)(s & 1) * STAGE_BYTES;
#pragma unroll
        for (int kk = 0; kk < 8; ++kk) {
            if (kk < 7) {
#pragma unroll
                for (int p = 0; p < 2; ++p)
                    bq[(kk + 1) & 1][p] = __ldg(Bf + bbase + (size_t)(kk + 1) * 512 + p * 32);
            }
            u32 ak = aCol + ((u32)kk << 5);
            u32 ah[4][4];
#pragma unroll
            for (int mt = 0; mt < 4; ++mt)
                ldsm4(ah[mt], abase + aRow[mt] + (ak ^ aXor[mt]));
#pragma unroll
            for (int p = 0; p < 2; ++p) {
                uint4 q = bq[kk & 1][p];
#pragma unroll
                for (int mt = 0; mt < 4; ++mt) {
                    mma16816(acc[mt][2 * p],     ah[mt], q.x, q.y);
                    mma16816(acc[mt][2 * p + 1], ah[mt], q.z, q.w);
                }
            }
        }
        __syncthreads();
    }

    // ---------------- epilogue ----------------
    const int baseN = nh * 128 + wn * 32 + 2 * (lane & 3);
#pragma unroll
    for (int mt = 0; mt < 4; ++mt) {
#pragma unroll
        for (int h = 0; h < 2; ++h) {
            int m = wm * 64 + mt * 16 + (lane >> 2) + h * 8;
            if (MODE == 0) {
                size_t gi = ((size_t)(b * 128 + y0) * 128 + m) * 256;
#pragma unroll
                for (int j = 0; j < 4; ++j) {
                    int n = baseN + j * 8;
                    float r0 = acc[mt][j][h * 2]     * dmod[b * 256 + n]     + bnoise[n];
                    float r1 = acc[mt][j][h * 2 + 1] * dmod[b * 256 + n + 1] + bnoise[n + 1];
                    r0 = (r0 >= 0.0f) ? r0 : 0.2f * r0;
                    r1 = (r1 >= 0.0f) ? r1 : 0.2f * r1;
                    u32 h0 = (u32)__half_as_ushort(__float2half(r0));
                    u32 h1 = (u32)__half_as_ushort(__float2half(r1));
                    *(u32*)(g_y1h + gi + n) = h0 | (h1 << 16);
                }
            } else {
#pragma unroll
                for (int j = 0; j < 4; ++j) {
                    int n = baseN + j * 8;
                    float r0 = acc[mt][j][h * 2]     * dmod[b * 256 + n]     + bnoise[n];
                    float r1 = acc[mt][j][h * 2 + 1] * dmod[b * 256 + n + 1] + bnoise[n + 1];
                    r0 = (r0 >= 0.0f) ? r0 : 0.2f * r0;
                    r1 = (r1 >= 0.0f) ? r1 : 0.2f * r1;
                    outp[((size_t)(b * 256 + n)     * 128 + y0) * 128 + m] = r0;
                    outp[((size_t)(b * 256 + n + 1) * 128 + y0) * 128 + m] = r1;
                }
            }
        }
    }
}

// ---------------- launch ----------------
extern "C" void kernel_launch(void* const* d_in, const int* in_sizes, int n_in,
                              void* d_out, int out_size) {
    (void)in_sizes; (void)n_in; (void)out_size;
    const float* x         = (const float*)d_in[0];
    const float* istyle    = (const float*)d_in[1];
    const float* w_style1  = (const float*)d_in[2];
    const float* b_style1  = (const float*)d_in[3];
    const float* w_style2  = (const float*)d_in[4];
    const float* b_style2  = (const float*)d_in[5];
    const float* b_noise1  = (const float*)d_in[7];
    const float* b_noise2  = (const float*)d_in[9];
    const float* conv1_w   = (const float*)d_in[10];
    const float* conv2_w   = (const float*)d_in[11];
    const float* conv1x1_w = (const float*)d_in[12];
    float* out = (float*)d_out;

    cudaFuncSetAttribute(k_convhmma<0>, cudaFuncAttributeMaxDynamicSharedMemorySize, SMEM_BYTES);
    cudaFuncSetAttribute(k_convhmma<1>, cudaFuncAttributeMaxDynamicSharedMemorySize, SMEM_BYTES);

    k_transpose<<<dim3(256, 16), 256>>>(x);
    k_uphalf<<<65536, 256>>>();
    k_styles<<<8, 256>>>(istyle, w_style1, b_style1, w_style2, b_style2);
    k_wsq<<<dim3(256, 2), 256>>>(conv1_w, conv2_w);
    k_demod<<<dim3(256, 4, 2), 256>>>();
    k_prepfrag<0><<<dim3(36, 16), 512>>>(conv1_w, nullptr);
    k_prepfrag<1><<<dim3(40, 16), 512>>>(conv2_w, conv1x1_w);
    k_convhmma<0><<<dim3(128, 2, 4), 256, SMEM_BYTES>>>(b_noise1, nullptr);
    k_convhmma<1><<<dim3(128, 2, 4), 256, SMEM_BYTES>>>(b_noise2, out);
}